// round 6
// baseline (speedup 1.0000x reference)
#include <cuda_runtime.h>
#include <math.h>
#include <stdint.h>

#define Bn 512
#define Cn 256
#define Ln 196
#define Dn 512
#define XST 260      // Xt stride (floats): 260 % 32 = 4  -> conflict-free frags
#define AST 108      // A_sm stride:       108 % 32 = 12  -> conflict-free
#define BST 200      // B_sm stride:       200 % 32 = 8   -> conflict-free
#define KP  104      // k-panel (13 mma k-steps)

// attn scratch: written then immediately re-read by the SAME CTA -> L2-resident
static __device__ float g_attn[(size_t)Bn * Ln * Ln];

// ============================ helpers ============================
__device__ __forceinline__ uint32_t f2tf(float f) {
    uint32_t r;
    asm("cvt.rna.tf32.f32 %0, %1;" : "=r"(r) : "f"(f));
    return r;
}
__device__ __forceinline__ uint32_t fu(float f) { return __float_as_uint(f); }

__device__ __forceinline__ void mma8(float* d, const uint32_t* a, const uint32_t* b) {
    asm volatile("mma.sync.aligned.m16n8k8.row.col.f32.tf32.tf32.f32 "
        "{%0,%1,%2,%3}, {%4,%5,%6,%7}, {%8,%9}, {%0,%1,%2,%3};"
        : "+f"(d[0]), "+f"(d[1]), "+f"(d[2]), "+f"(d[3])
        : "r"(a[0]), "r"(a[1]), "r"(a[2]), "r"(a[3]), "r"(b[0]), "r"(b[1]));
}

// ============================================================================
// Mega-kernel: one CTA per batch, 256 threads, all phases fused.
// ============================================================================
__global__ __launch_bounds__(256, 1) void k_main(
    const float* __restrict__ imf, const float* __restrict__ txt,
    const float* __restrict__ sam, const float* __restrict__ Wsim,
    const float* __restrict__ bsim, float* __restrict__ out)
{
    extern __shared__ float dyn[];                 // 216,320 B
    __shared__ float s_im[Dn];
    __shared__ float red[3][8];
    __shared__ float s_simw[200];
    __shared__ __align__(16) float cs1[200];
    __shared__ __align__(16) float cs2[200];

    int b = blockIdx.x, t = threadIdx.x, w = t >> 5, ln = t & 31;
    int g = ln >> 2, tig = ln & 3;
    const float* Sb = sam + (size_t)b * Cn * Ln;
    float* At = g_attn + (size_t)b * Ln * Ln;

    // ---------------- Phase 0: simw -> s_simw ----------------
    {
        const float* ib = imf + (size_t)b * Dn;
        const float* tb = txt + (size_t)b * Dn;
        float a0 = ib[t], a1 = ib[t + 256];
        float c0 = tb[t], c1 = tb[t + 256];
        float ni = a0*a0 + a1*a1, nt = c0*c0 + c1*c1, ct = a0*c0 + a1*c1;
        #pragma unroll
        for (int o = 16; o > 0; o >>= 1) {
            ni += __shfl_xor_sync(0xffffffffu, ni, o);
            nt += __shfl_xor_sync(0xffffffffu, nt, o);
            ct += __shfl_xor_sync(0xffffffffu, ct, o);
        }
        if (ln == 0) { red[0][w] = ni; red[1][w] = nt; red[2][w] = ct; }
        __syncthreads();
        float nI = 0.f, nT = 0.f, cT = 0.f;
        #pragma unroll
        for (int j = 0; j < 8; j++) { nI += red[0][j]; nT += red[1][j]; cT += red[2][j]; }
        float invI = 1.0f / fmaxf(sqrtf(nI), 1e-12f);
        float invT = 1.0f / fmaxf(sqrtf(nT), 1e-12f);
        float cross = cT * invI * invT;
        s_im[t] = a0 * invI; s_im[t + 256] = a1 * invI;
        if (t < 200) { cs1[t] = 0.f; cs2[t] = 0.f; }
        __syncthreads();

        const float4* s4 = reinterpret_cast<const float4*>(s_im);
        for (int r = w; r < Ln; r += 8) {
            const float4* wr = reinterpret_cast<const float4*>(Wsim + (size_t)r * Dn);
            float acc = 0.f;
            #pragma unroll
            for (int i = 0; i < 4; i++) {
                float4 a = wr[ln + i * 32];
                float4 s = s4[ln + i * 32];
                acc += a.x*s.x + a.y*s.y + a.z*s.z + a.w*s.w;
            }
            #pragma unroll
            for (int o = 16; o > 0; o >>= 1) acc += __shfl_xor_sync(0xffffffffu, acc, o);
            if (ln == 0) {
                acc += bsim[r];
                s_simw[r] = cross * (1.0f / (1.0f + __expf(-acc))) * 0.1f;
            }
        }
    }
    __syncthreads();

    // ---------------- Phase 1: scores + softmax -> g_attn (L2) ----------------
    {
        float* Xt = dyn;   // 208 x XST
        for (int i = t; i < 12 * XST; i += 256) Xt[196 * XST + i] = 0.f;
        for (int idx = t; idx < Cn * 49; idx += 256) {
            int c = idx / 49, l4 = idx % 49;
            float4 v = reinterpret_cast<const float4*>(Sb)[idx];
            int l = l4 * 4;
            Xt[(l+0)*XST + c] = v.x; Xt[(l+1)*XST + c] = v.y;
            Xt[(l+2)*XST + c] = v.z; Xt[(l+3)*XST + c] = v.w;
        }
        __syncthreads();

        for (int l = w; l < Ln; l += 8) {
            float4* row4 = reinterpret_cast<float4*>(Xt + l * XST);
            float4 v0 = row4[ln], v1 = row4[ln + 32];
            float s = v0.x*v0.x + v0.y*v0.y + v0.z*v0.z + v0.w*v0.w
                    + v1.x*v1.x + v1.y*v1.y + v1.z*v1.z + v1.w*v1.w;
            #pragma unroll
            for (int o = 16; o > 0; o >>= 1) s += __shfl_xor_sync(0xffffffffu, s, o);
            float iv = 0.25f / fmaxf(sqrtf(s), 1e-12f);
            float4 o0, o1;
            o0.x = __uint_as_float(f2tf(v0.x * iv)); o0.y = __uint_as_float(f2tf(v0.y * iv));
            o0.z = __uint_as_float(f2tf(v0.z * iv)); o0.w = __uint_as_float(f2tf(v0.w * iv));
            o1.x = __uint_as_float(f2tf(v1.x * iv)); o1.y = __uint_as_float(f2tf(v1.y * iv));
            o1.z = __uint_as_float(f2tf(v1.z * iv)); o1.w = __uint_as_float(f2tf(v1.w * iv));
            row4[ln] = o0; row4[ln + 32] = o1;
        }
        __syncthreads();

        for (int mt = w; mt < 13; mt += 8) {
            float acc[25][4];
            #pragma unroll
            for (int n = 0; n < 25; n++)
                #pragma unroll
                for (int j = 0; j < 4; j++) acc[n][j] = 0.f;

            const float* A0 = Xt + (mt * 16 + g) * XST;
            const float* A1 = A0 + 8 * XST;
            for (int ks = 0; ks < 32; ks++) {
                int k0 = ks * 8;
                uint32_t a[4] = { fu(A0[k0 + tig]), fu(A1[k0 + tig]),
                                  fu(A0[k0 + tig + 4]), fu(A1[k0 + tig + 4]) };
                #pragma unroll
                for (int n = 0; n < 25; n++) {
                    const float* Bp = Xt + (n * 8 + g) * XST + k0 + tig;
                    uint32_t bb[2] = { fu(Bp[0]), fu(Bp[4]) };
                    mma8(acc[n], a, bb);
                }
            }

            #pragma unroll
            for (int rh = 0; rh < 2; rh++) {
                int l = mt * 16 + g + 8 * rh;
                float mx = -3.0e38f;
                #pragma unroll
                for (int n = 0; n < 25; n++) {
                    int col0 = n * 8 + 2 * tig;
                    if (col0 < Ln) {
                        mx = fmaxf(mx, acc[n][rh*2]);
                        mx = fmaxf(mx, acc[n][rh*2+1]);
                    }
                }
                mx = fmaxf(mx, __shfl_xor_sync(0xffffffffu, mx, 1));
                mx = fmaxf(mx, __shfl_xor_sync(0xffffffffu, mx, 2));
                float sum = 0.f;
                #pragma unroll
                for (int n = 0; n < 25; n++) {
                    int col0 = n * 8 + 2 * tig;
                    if (col0 < Ln) {
                        float e0 = __expf(acc[n][rh*2]   - mx);
                        float e1 = __expf(acc[n][rh*2+1] - mx);
                        acc[n][rh*2] = e0; acc[n][rh*2+1] = e1;
                        sum += e0 + e1;
                    }
                }
                sum += __shfl_xor_sync(0xffffffffu, sum, 1);
                sum += __shfl_xor_sync(0xffffffffu, sum, 2);
                float is = 1.0f / sum;
                if (l < Ln) {
                    float* ar = At + (size_t)l * Ln;
                    #pragma unroll
                    for (int n = 0; n < 25; n++) {
                        int col0 = n * 8 + 2 * tig;
                        if (col0 < Ln)
                            *reinterpret_cast<float2*>(ar + col0) =
                                make_float2(acc[n][rh*2] * is, acc[n][rh*2+1] * is);
                    }
                }
            }
        }
    }
    __syncthreads();

    // ---------------- Phase 2: B = attn (tf32) resident; weighted GEMM ----------------
    {
        float* B_sm = dyn;                  // 200 x BST (rows 196..199 zero)
        float* A_sm = dyn + 200 * BST;      // 128 x AST

        for (int idx = t; idx < 200 * 50; idx += 256) {
            int kk = idx / 50, ch = idx % 50;
            float4 v = make_float4(0.f, 0.f, 0.f, 0.f);
            if (kk < Ln && ch < 49) v = *reinterpret_cast<const float4*>(At + (size_t)kk * Ln + ch * 4);
            float* dst = B_sm + kk * BST + ch * 4;
            dst[0] = __uint_as_float(f2tf(v.x)); dst[1] = __uint_as_float(f2tf(v.y));
            dst[2] = __uint_as_float(f2tf(v.z)); dst[3] = __uint_as_float(f2tf(v.w));
        }

        for (int p = 0; p < 2; p++) {
            float acc[25][4];
            #pragma unroll
            for (int n = 0; n < 25; n++)
                #pragma unroll
                for (int j = 0; j < 4; j++) acc[n][j] = 0.f;

            for (int kh = 0; kh < 2; kh++) {
                __syncthreads();
                for (int idx = t; idx < 128 * 26; idx += 256) {
                    int cr = idx / 26, ch = idx % 26;
                    int gk = kh * KP + ch * 4;
                    float4 v = make_float4(0.f, 0.f, 0.f, 0.f);
                    if (gk < Ln) v = *reinterpret_cast<const float4*>(Sb + (size_t)(p*128 + cr) * Ln + gk);
                    float* dst = A_sm + cr * AST + ch * 4;
                    dst[0] = __uint_as_float(f2tf(v.x)); dst[1] = __uint_as_float(f2tf(v.y));
                    dst[2] = __uint_as_float(f2tf(v.z)); dst[3] = __uint_as_float(f2tf(v.w));
                }
                __syncthreads();

                int nsteps = kh ? 12 : 13;
                const float* A0 = A_sm + (w * 16 + g) * AST;
                const float* A1 = A0 + 8 * AST;
                for (int ks = 0; ks < nsteps; ks++) {
                    int k0 = ks * 8;
                    int gk0 = kh * KP + k0;
                    uint32_t a[4] = { fu(A0[k0 + tig]), fu(A1[k0 + tig]),
                                      fu(A0[k0 + tig + 4]), fu(A1[k0 + tig + 4]) };
                    #pragma unroll
                    for (int n = 0; n < 25; n++) {
                        const float* Bp = B_sm + (gk0 + tig) * BST + n * 8 + g;
                        uint32_t bb[2] = { fu(Bp[0]), fu(Bp[4 * BST]) };
                        mma8(acc[n], a, bb);
                    }
                }
            }

            // epilogue: y = sam + D -> out; column stats via quad shuffles
            int c0r = p * 128 + w * 16 + g;
            int c1r = c0r + 8;
            const float* S0 = Sb + (size_t)c0r * Ln;
            const float* S1 = Sb + (size_t)c1r * Ln;
            float* O0 = out + ((size_t)b * Cn + c0r) * Ln;
            float* O1 = out + ((size_t)b * Cn + c1r) * Ln;
            #pragma unroll
            for (int n = 0; n < 25; n++) {
                int col0 = n * 8 + 2 * tig;
                bool v = col0 < Ln;
                float y0 = 0.f, y1 = 0.f, y2 = 0.f, y3 = 0.f;
                if (v) {
                    float2 s0 = *reinterpret_cast<const float2*>(S0 + col0);
                    float2 s1 = *reinterpret_cast<const float2*>(S1 + col0);
                    y0 = s0.x + acc[n][0]; y1 = s0.y + acc[n][1];
                    y2 = s1.x + acc[n][2]; y3 = s1.y + acc[n][3];
                    *reinterpret_cast<float2*>(O0 + col0) = make_float2(y0, y1);
                    *reinterpret_cast<float2*>(O1 + col0) = make_float2(y2, y3);
                }
                float sa0 = y0 + y2, sa1 = y1 + y3;
                float sq0 = y0*y0 + y2*y2, sq1 = y1*y1 + y3*y3;
                #pragma unroll
                for (int o = 4; o < 32; o <<= 1) {
                    sa0 += __shfl_xor_sync(0xffffffffu, sa0, o);
                    sa1 += __shfl_xor_sync(0xffffffffu, sa1, o);
                    sq0 += __shfl_xor_sync(0xffffffffu, sq0, o);
                    sq1 += __shfl_xor_sync(0xffffffffu, sq1, o);
                }
                if (g == 0 && v) {
                    atomicAdd(&cs1[col0], sa0);     atomicAdd(&cs1[col0 + 1], sa1);
                    atomicAdd(&cs2[col0], sq0);     atomicAdd(&cs2[col0 + 1], sq1);
                }
            }
        }
    }
    __syncthreads();

    // ---------------- Phase 3: channel-LN affine P,Q (into cs1/cs2) ----------------
    if (t < Ln) {
        float a = 0.5f * s_simw[t];
        float mu_y  = cs1[t] * (1.0f / Cn);
        float var_y = cs2[t] * (1.0f / Cn) - mu_y * mu_y;
        float inv_s = rsqrtf(a * a * var_y + 1e-5f);
        cs1[t] = a * inv_s;
        cs2[t] = -a * mu_y * inv_s;
    }
    if (t >= Ln && t < 200) { cs1[t] = 0.f; cs2[t] = 0.f; }
    __syncthreads();

    // ---------------- Phase 4: spatial standardization (out is L2-hot) ----------------
    {
        const float4* P4 = reinterpret_cast<const float4*>(cs1);
        const float4* Q4 = reinterpret_cast<const float4*>(cs2);
        bool has2 = (ln + 32) < Ln / 4;
        int g2 = has2 ? (ln + 32) : 0;
        float4 p0 = P4[ln], q0 = Q4[ln];
        float4 p1 = P4[g2], q1 = Q4[g2];

        for (int c = w; c < Cn; c += 8) {
            float4* orow = reinterpret_cast<float4*>(out + ((size_t)b * Cn + c) * Ln);
            float4 y0 = orow[ln];
            float x0[4] = { fmaf(y0.x, p0.x, q0.x), fmaf(y0.y, p0.y, q0.y),
                            fmaf(y0.z, p0.z, q0.z), fmaf(y0.w, p0.w, q0.w) };
            float x1[4] = { 0.f, 0.f, 0.f, 0.f };
            if (has2) {
                float4 y1 = orow[g2];
                x1[0] = fmaf(y1.x, p1.x, q1.x); x1[1] = fmaf(y1.y, p1.y, q1.y);
                x1[2] = fmaf(y1.z, p1.z, q1.z); x1[3] = fmaf(y1.w, p1.w, q1.w);
            }
            float s1 = x0[0] + x0[1] + x0[2] + x0[3];
            float s2 = x0[0]*x0[0] + x0[1]*x0[1] + x0[2]*x0[2] + x0[3]*x0[3];
            if (has2) {
                s1 += x1[0] + x1[1] + x1[2] + x1[3];
                s2 += x1[0]*x1[0] + x1[1]*x1[1] + x1[2]*x1[2] + x1[3]*x1[3];
            }
            #pragma unroll
            for (int o = 16; o > 0; o >>= 1) {
                s1 += __shfl_xor_sync(0xffffffffu, s1, o);
                s2 += __shfl_xor_sync(0xffffffffu, s2, o);
            }
            float mean = s1 * (1.0f / Ln);
            float var  = (s2 - (float)Ln * mean * mean) * (1.0f / (Ln - 1));
            float inv  = 1.0f / (sqrtf(fmaxf(var, 0.f)) + 1e-6f);

            float4 o0 = { (x0[0]-mean)*inv, (x0[1]-mean)*inv, (x0[2]-mean)*inv, (x0[3]-mean)*inv };
            orow[ln] = o0;
            if (has2) {
                float4 o1 = { (x1[0]-mean)*inv, (x1[1]-mean)*inv, (x1[2]-mean)*inv, (x1[3]-mean)*inv };
                orow[g2] = o1;
            }
        }
    }
}

// ============================================================================
extern "C" void kernel_launch(void* const* d_in, const int* in_sizes, int n_in,
                              void* d_out, int out_size)
{
    const float* imf  = (const float*)d_in[0];
    const float* txt  = (const float*)d_in[1];
    const float* sam  = (const float*)d_in[2];
    const float* Wsim = (const float*)d_in[3];
    const float* bsim = (const float*)d_in[4];
    float* out = (float*)d_out;

    const int smem = 208 * XST * (int)sizeof(float);   // 216,320 B (>= 200*BST+128*AST)
    cudaFuncSetAttribute(k_main, cudaFuncAttributeMaxDynamicSharedMemorySize, smem);
    k_main<<<Bn, 256, smem>>>(imf, txt, sam, Wsim, bsim, out);
}

// round 7
// speedup vs baseline: 1.1476x; 1.1476x over previous
#include <cuda_runtime.h>
#include <math.h>
#include <stdint.h>

#define Bn 512
#define Cn 256
#define Ln 196
#define Dn 512
#define XST 260      // Xt stride: 260 % 32 = 4  -> conflict-free frag loads
#define BST 200      // B_sm stride: 200 % 32 = 8 -> conflict-free
#define AST 60       // A_sm stride: 60 % 32 = 28 -> conflict-free
#define KPN 56       // A k-panel width

// raw exp scratch: written then re-read by the SAME CTA -> L2-resident
static __device__ float g_attn[(size_t)Bn * Ln * Ln];

__device__ __forceinline__ uint32_t f2tf(float f) {
    uint32_t r;
    asm("cvt.rna.tf32.f32 %0, %1;" : "=r"(r) : "f"(f));
    return r;
}
__device__ __forceinline__ uint32_t fu(float f) { return __float_as_uint(f); }

__device__ __forceinline__ void mma8(float* d, const uint32_t* a, const uint32_t* b) {
    asm volatile("mma.sync.aligned.m16n8k8.row.col.f32.tf32.tf32.f32 "
        "{%0,%1,%2,%3}, {%4,%5,%6,%7}, {%8,%9}, {%0,%1,%2,%3};"
        : "+f"(d[0]), "+f"(d[1]), "+f"(d[2]), "+f"(d[3])
        : "r"(a[0]), "r"(a[1]), "r"(a[2]), "r"(a[3]), "r"(b[0]), "r"(b[1]));
}

// ============================================================================
// Mega-kernel: one CTA per batch, 512 threads (16 warps).
// ============================================================================
__global__ __launch_bounds__(512, 1) void k_main(
    const float* __restrict__ imf, const float* __restrict__ txt,
    const float* __restrict__ sam, const float* __restrict__ Wsim,
    const float* __restrict__ bsim, float* __restrict__ out)
{
    extern __shared__ float dyn[];                 // 221,440 B
    __shared__ float s_im[Dn];
    __shared__ float red[3][16];
    __shared__ float s_simw[200];
    __shared__ __align__(16) float cs1[200];
    __shared__ __align__(16) float cs2[200];
    __shared__ float s_rsum[208];

    int b = blockIdx.x, t = threadIdx.x, w = t >> 5, ln = t & 31;
    int g = ln >> 2, tig = ln & 3;
    const float* Sb = sam + (size_t)b * Cn * Ln;
    float* At = g_attn + (size_t)b * Ln * Ln;

    // ---------------- Phase 0: simw -> s_simw; zero accumulators ----------------
    {
        const float* ib = imf + (size_t)b * Dn;
        const float* tb = txt + (size_t)b * Dn;
        float a0 = ib[t], c0 = tb[t];
        float ni = a0*a0, nt = c0*c0, ct = a0*c0;
        #pragma unroll
        for (int o = 16; o > 0; o >>= 1) {
            ni += __shfl_xor_sync(0xffffffffu, ni, o);
            nt += __shfl_xor_sync(0xffffffffu, nt, o);
            ct += __shfl_xor_sync(0xffffffffu, ct, o);
        }
        if (ln == 0) { red[0][w] = ni; red[1][w] = nt; red[2][w] = ct; }
        if (t < 200) { cs1[t] = 0.f; cs2[t] = 0.f; }
        if (t < 208) s_rsum[t] = 0.f;
        __syncthreads();
        float nI = 0.f, nT = 0.f, cT = 0.f;
        #pragma unroll
        for (int j = 0; j < 16; j++) { nI += red[0][j]; nT += red[1][j]; cT += red[2][j]; }
        float invI = 1.0f / fmaxf(sqrtf(nI), 1e-12f);
        float invT = 1.0f / fmaxf(sqrtf(nT), 1e-12f);
        float cross = cT * invI * invT;
        s_im[t] = a0 * invI;
        __syncthreads();

        const float4* s4 = reinterpret_cast<const float4*>(s_im);
        for (int r = w; r < Ln; r += 16) {
            const float4* wr = reinterpret_cast<const float4*>(Wsim + (size_t)r * Dn);
            float acc = 0.f;
            #pragma unroll
            for (int i = 0; i < 4; i++) {
                float4 a = wr[ln + i * 32];
                float4 s = s4[ln + i * 32];
                acc += a.x*s.x + a.y*s.y + a.z*s.z + a.w*s.w;
            }
            #pragma unroll
            for (int o = 16; o > 0; o >>= 1) acc += __shfl_xor_sync(0xffffffffu, acc, o);
            if (ln == 0) {
                acc += bsim[r];
                s_simw[r] = cross * (1.0f / (1.0f + __expf(-acc))) * 0.1f;
            }
        }
    }
    __syncthreads();

    // ---------------- Phase 1: raw exp(scores) -> g_attn; row sums -> s_rsum ----
    {
        float* Xt = dyn;   // 208 x XST
        for (int i = t; i < 12 * XST; i += 512) Xt[196 * XST + i] = 0.f;
        for (int idx = t; idx < Cn * 49; idx += 512) {
            int c = idx / 49, l4 = idx % 49;
            float4 v = reinterpret_cast<const float4*>(Sb)[idx];
            int l = l4 * 4;
            Xt[(l+0)*XST + c] = v.x; Xt[(l+1)*XST + c] = v.y;
            Xt[(l+2)*XST + c] = v.z; Xt[(l+3)*XST + c] = v.w;
        }
        __syncthreads();

        for (int l = w; l < Ln; l += 16) {
            float4* row4 = reinterpret_cast<float4*>(Xt + l * XST);
            float4 v0 = row4[ln], v1 = row4[ln + 32];
            float s = v0.x*v0.x + v0.y*v0.y + v0.z*v0.z + v0.w*v0.w
                    + v1.x*v1.x + v1.y*v1.y + v1.z*v1.z + v1.w*v1.w;
            #pragma unroll
            for (int o = 16; o > 0; o >>= 1) s += __shfl_xor_sync(0xffffffffu, s, o);
            float iv = 0.25f / fmaxf(sqrtf(s), 1e-12f);
            float4 o0, o1;
            o0.x = __uint_as_float(f2tf(v0.x * iv)); o0.y = __uint_as_float(f2tf(v0.y * iv));
            o0.z = __uint_as_float(f2tf(v0.z * iv)); o0.w = __uint_as_float(f2tf(v0.w * iv));
            o1.x = __uint_as_float(f2tf(v1.x * iv)); o1.y = __uint_as_float(f2tf(v1.y * iv));
            o1.z = __uint_as_float(f2tf(v1.z * iv)); o1.w = __uint_as_float(f2tf(v1.w * iv));
            row4[ln] = o0; row4[ln + 32] = o1;
        }
        __syncthreads();

        // jobs: 0..12 -> (mt=j, half 0, 13 frags), 13..25 -> (mt=j-13, half 1, 12 frags)
        for (int job = w; job < 26; job += 16) {
            int mt   = (job < 13) ? job : job - 13;
            int half = (job < 13) ? 0 : 1;
            int nfr  = half ? 12 : 13;
            int cbase = half * 104;

            float acc[13][4];
            #pragma unroll
            for (int n = 0; n < 13; n++)
                #pragma unroll
                for (int j = 0; j < 4; j++) acc[n][j] = 0.f;

            const float* A0 = Xt + (mt * 16 + g) * XST;
            const float* A1 = A0 + 8 * XST;
            for (int ks = 0; ks < 32; ks++) {
                int k0 = ks * 8;
                uint32_t a[4] = { fu(A0[k0 + tig]), fu(A1[k0 + tig]),
                                  fu(A0[k0 + tig + 4]), fu(A1[k0 + tig + 4]) };
                for (int n = 0; n < nfr; n++) {
                    const float* Bp = Xt + (cbase + n * 8 + g) * XST + k0 + tig;
                    uint32_t bb[2] = { fu(Bp[0]), fu(Bp[4]) };
                    mma8(acc[n], a, bb);
                }
            }

            #pragma unroll
            for (int rh = 0; rh < 2; rh++) {
                int l = mt * 16 + g + 8 * rh;
                float sum = 0.f;
                for (int n = 0; n < nfr; n++) {
                    int col0 = cbase + n * 8 + 2 * tig;
                    float e0 = __expf(acc[n][rh*2]);
                    float e1 = __expf(acc[n][rh*2+1]);
                    acc[n][rh*2] = e0; acc[n][rh*2+1] = e1;
                    if (col0 < Ln) sum += e0 + e1;
                }
                sum += __shfl_xor_sync(0xffffffffu, sum, 1);
                sum += __shfl_xor_sync(0xffffffffu, sum, 2);
                if (l < Ln) {
                    if (tig == 0) atomicAdd(&s_rsum[l], sum);
                    float* ar = At + (size_t)l * Ln;
                    for (int n = 0; n < nfr; n++) {
                        int col0 = cbase + n * 8 + 2 * tig;
                        if (col0 < Ln)
                            *reinterpret_cast<float2*>(ar + col0) =
                                make_float2(acc[n][rh*2], acc[n][rh*2+1]);
                    }
                }
            }
        }
    }
    __syncthreads();
    if (t < Ln) s_rsum[t] = 1.0f / s_rsum[t];
    __syncthreads();

    // ---------------- Phase 2: weighted GEMM; y -> out; column stats ------------
    {
        float* B_sm = dyn;                   // 200 x BST (rows/cols >=196 zero)
        float* A_sm = dyn + 200 * BST;       // 256 x AST

        // stage B = attn (normalized here) as tf32
        for (int idx = t; idx < 200 * 50; idx += 512) {
            int kk = idx / 50, ch = idx % 50;
            float4 v = make_float4(0.f, 0.f, 0.f, 0.f);
            if (kk < Ln && ch < 49) {
                v = *reinterpret_cast<const float4*>(At + (size_t)kk * Ln + ch * 4);
                float is = s_rsum[kk];
                v.x *= is; v.y *= is; v.z *= is; v.w *= is;
            }
            float* dst = B_sm + kk * BST + ch * 4;
            dst[0] = __uint_as_float(f2tf(v.x)); dst[1] = __uint_as_float(f2tf(v.y));
            dst[2] = __uint_as_float(f2tf(v.z)); dst[3] = __uint_as_float(f2tf(v.w));
        }

        const int l0s[4]    = { 0, 56, 112, 168 };
        const int nsteps[4] = { 7, 7, 7, 4 };

        for (int h = 0; h < 2; h++) {
            int nfr = h ? 12 : 13;
            int cbase = h * 104;
            float acc[13][4];
            #pragma unroll
            for (int n = 0; n < 13; n++)
                #pragma unroll
                for (int j = 0; j < 4; j++) acc[n][j] = 0.f;

            for (int p = 0; p < 4; p++) {
                int l0 = l0s[p];
                __syncthreads();
                for (int idx = t; idx < 256 * 14; idx += 512) {
                    int cr = idx / 14, ch = idx % 14;
                    int gk = l0 + ch * 4;
                    float4 v = make_float4(0.f, 0.f, 0.f, 0.f);
                    if (gk < Ln) v = *reinterpret_cast<const float4*>(Sb + (size_t)cr * Ln + gk);
                    float* dst = A_sm + cr * AST + ch * 4;
                    dst[0] = __uint_as_float(f2tf(v.x)); dst[1] = __uint_as_float(f2tf(v.y));
                    dst[2] = __uint_as_float(f2tf(v.z)); dst[3] = __uint_as_float(f2tf(v.w));
                }
                __syncthreads();

                const float* A0 = A_sm + (w * 16 + g) * AST;
                const float* A1 = A0 + 8 * AST;
                for (int ks = 0; ks < nsteps[p]; ks++) {
                    int k0 = ks * 8;
                    const float* Brow = B_sm + (l0 + k0 + tig) * BST + cbase + g;
                    uint32_t a[4] = { fu(A0[k0 + tig]), fu(A1[k0 + tig]),
                                      fu(A0[k0 + tig + 4]), fu(A1[k0 + tig + 4]) };
                    for (int n = 0; n < nfr; n++) {
                        uint32_t bb[2] = { fu(Brow[n * 8]), fu(Brow[n * 8 + 4 * BST]) };
                        mma8(acc[n], a, bb);
                    }
                }
            }

            // epilogue for this half: y = sam + D -> out; column stats
            int c0r = w * 16 + g;
            int c1r = c0r + 8;
            const float* S0 = Sb + (size_t)c0r * Ln;
            const float* S1 = Sb + (size_t)c1r * Ln;
            float* O0 = out + ((size_t)b * Cn + c0r) * Ln;
            float* O1 = out + ((size_t)b * Cn + c1r) * Ln;
            for (int n = 0; n < nfr; n++) {
                int col0 = cbase + n * 8 + 2 * tig;
                bool v = col0 < Ln;
                float y0 = 0.f, y1 = 0.f, y2 = 0.f, y3 = 0.f;
                if (v) {
                    float2 s0 = *reinterpret_cast<const float2*>(S0 + col0);
                    float2 s1 = *reinterpret_cast<const float2*>(S1 + col0);
                    y0 = s0.x + acc[n][0]; y1 = s0.y + acc[n][1];
                    y2 = s1.x + acc[n][2]; y3 = s1.y + acc[n][3];
                    *reinterpret_cast<float2*>(O0 + col0) = make_float2(y0, y1);
                    *reinterpret_cast<float2*>(O1 + col0) = make_float2(y2, y3);
                }
                float sa0 = y0 + y2, sa1 = y1 + y3;
                float sq0 = y0*y0 + y2*y2, sq1 = y1*y1 + y3*y3;
                #pragma unroll
                for (int o = 4; o < 32; o <<= 1) {
                    sa0 += __shfl_xor_sync(0xffffffffu, sa0, o);
                    sa1 += __shfl_xor_sync(0xffffffffu, sa1, o);
                    sq0 += __shfl_xor_sync(0xffffffffu, sq0, o);
                    sq1 += __shfl_xor_sync(0xffffffffu, sq1, o);
                }
                if (g == 0 && v) {
                    atomicAdd(&cs1[col0], sa0);     atomicAdd(&cs1[col0 + 1], sa1);
                    atomicAdd(&cs2[col0], sq0);     atomicAdd(&cs2[col0 + 1], sq1);
                }
            }
        }
    }
    __syncthreads();

    // ---------------- Phase 3: channel-LN affine P,Q ----------------
    if (t < Ln) {
        float a = 0.5f * s_simw[t];
        float mu_y  = cs1[t] * (1.0f / Cn);
        float var_y = cs2[t] * (1.0f / Cn) - mu_y * mu_y;
        float inv_s = rsqrtf(a * a * var_y + 1e-5f);
        cs1[t] = a * inv_s;
        cs2[t] = -a * mu_y * inv_s;
    }
    if (t >= Ln && t < 200) { cs1[t] = 0.f; cs2[t] = 0.f; }
    __syncthreads();

    // ---------------- Phase 4: spatial standardization (out L2-hot) -------------
    {
        const float4* P4 = reinterpret_cast<const float4*>(cs1);
        const float4* Q4 = reinterpret_cast<const float4*>(cs2);
        bool has2 = (ln + 32) < Ln / 4;
        int g2 = has2 ? (ln + 32) : 0;
        float4 p0 = P4[ln], q0 = Q4[ln];
        float4 p1 = P4[g2], q1 = Q4[g2];

        for (int c = w; c < Cn; c += 16) {
            float4* orow = reinterpret_cast<float4*>(out + ((size_t)b * Cn + c) * Ln);
            float4 y0 = orow[ln];
            float x0[4] = { fmaf(y0.x, p0.x, q0.x), fmaf(y0.y, p0.y, q0.y),
                            fmaf(y0.z, p0.z, q0.z), fmaf(y0.w, p0.w, q0.w) };
            float x1[4] = { 0.f, 0.f, 0.f, 0.f };
            if (has2) {
                float4 y1 = orow[g2];
                x1[0] = fmaf(y1.x, p1.x, q1.x); x1[1] = fmaf(y1.y, p1.y, q1.y);
                x1[2] = fmaf(y1.z, p1.z, q1.z); x1[3] = fmaf(y1.w, p1.w, q1.w);
            }
            float s1 = x0[0] + x0[1] + x0[2] + x0[3];
            float s2 = x0[0]*x0[0] + x0[1]*x0[1] + x0[2]*x0[2] + x0[3]*x0[3];
            if (has2) {
                s1 += x1[0] + x1[1] + x1[2] + x1[3];
                s2 += x1[0]*x1[0] + x1[1]*x1[1] + x1[2]*x1[2] + x1[3]*x1[3];
            }
            #pragma unroll
            for (int o = 16; o > 0; o >>= 1) {
                s1 += __shfl_xor_sync(0xffffffffu, s1, o);
                s2 += __shfl_xor_sync(0xffffffffu, s2, o);
            }
            float mean = s1 * (1.0f / Ln);
            float var  = (s2 - (float)Ln * mean * mean) * (1.0f / (Ln - 1));
            float inv  = 1.0f / (sqrtf(fmaxf(var, 0.f)) + 1e-6f);

            float4 o0 = { (x0[0]-mean)*inv, (x0[1]-mean)*inv, (x0[2]-mean)*inv, (x0[3]-mean)*inv };
            orow[ln] = o0;
            if (has2) {
                float4 o1 = { (x1[0]-mean)*inv, (x1[1]-mean)*inv, (x1[2]-mean)*inv, (x1[3]-mean)*inv };
                orow[g2] = o1;
            }
        }
    }
}

// ============================================================================
extern "C" void kernel_launch(void* const* d_in, const int* in_sizes, int n_in,
                              void* d_out, int out_size)
{
    const float* imf  = (const float*)d_in[0];
    const float* txt  = (const float*)d_in[1];
    const float* sam  = (const float*)d_in[2];
    const float* Wsim = (const float*)d_in[3];
    const float* bsim = (const float*)d_in[4];
    float* out = (float*)d_out;

    // max(phase1: 208*XST*4 = 216320, phase2: (200*BST + 256*AST)*4 = 221440)
    const int smem = 221440;
    cudaFuncSetAttribute(k_main, cudaFuncAttributeMaxDynamicSharedMemorySize, smem);
    k_main<<<Bn, 512, smem>>>(imf, txt, sam, Wsim, bsim, out);
}

// round 8
// speedup vs baseline: 1.2044x; 1.0495x over previous
#include <cuda_runtime.h>
#include <cuda_bf16.h>
#include <math.h>
#include <stdint.h>

#define Bn 512
#define Cn 256
#define Ln 196
#define Dn 512
#define XWST 136   // Xt word stride (uint32): 68 8B-units ≡ 4 mod 16 -> 2-way floor
#define BST  200   // B_sm float stride: 100 units ≡ 4
#define AST  40    // A_sm float stride: 20 units ≡ 4

// raw exp scratch (SYMMETRIC matrix; same-CTA reuse -> L2-resident)
static __device__ float g_attn[(size_t)Bn * Ln * Ln];

__device__ __forceinline__ uint32_t f2tf(float f) {
    uint32_t r;
    asm("cvt.rna.tf32.f32 %0, %1;" : "=r"(r) : "f"(f));
    return r;
}
__device__ __forceinline__ uint32_t fu(float f) { return __float_as_uint(f); }
// k-permutation within 8-groups: thread tig's pair (k=tig, k=tig+4) adjacent
__device__ __forceinline__ int pidx(int l) {
    return (l & ~7) + ((l & 3) << 1) + ((l >> 2) & 1);
}

__device__ __forceinline__ void mma8(float* d, uint32_t a0, uint32_t a1, uint32_t a2,
                                     uint32_t a3, uint32_t b0, uint32_t b1) {
    asm volatile("mma.sync.aligned.m16n8k8.row.col.f32.tf32.tf32.f32 "
        "{%0,%1,%2,%3}, {%4,%5,%6,%7}, {%8,%9}, {%0,%1,%2,%3};"
        : "+f"(d[0]), "+f"(d[1]), "+f"(d[2]), "+f"(d[3])
        : "r"(a0), "r"(a1), "r"(a2), "r"(a3), "r"(b0), "r"(b1));
}
__device__ __forceinline__ void mma16(float* d, uint32_t a0, uint32_t a1, uint32_t a2,
                                      uint32_t a3, uint32_t b0, uint32_t b1) {
    asm volatile("mma.sync.aligned.m16n8k16.row.col.f32.bf16.bf16.f32 "
        "{%0,%1,%2,%3}, {%4,%5,%6,%7}, {%8,%9}, {%0,%1,%2,%3};"
        : "+f"(d[0]), "+f"(d[1]), "+f"(d[2]), "+f"(d[3])
        : "r"(a0), "r"(a1), "r"(a2), "r"(a3), "r"(b0), "r"(b1));
}

// ============================================================================
// Mega-kernel: one CTA per batch, 512 threads.
// ============================================================================
__global__ __launch_bounds__(512, 1) void k_main(
    const float* __restrict__ imf, const float* __restrict__ txt,
    const float* __restrict__ sam, const float* __restrict__ Wsim,
    const float* __restrict__ bsim, float* __restrict__ out)
{
    extern __shared__ float dyn[];          // 200,960 B
    __shared__ float s_im[Dn];
    __shared__ float red[3][16];
    __shared__ float s_simw[200];
    __shared__ __align__(16) float cs1[200];
    __shared__ __align__(16) float cs2[200];
    __shared__ float s_rsum[208];
    __shared__ float s_inv[200];

    int b = blockIdx.x, t = threadIdx.x, w = t >> 5, ln = t & 31;
    int g = ln >> 2, tig = ln & 3;
    const float* Sb = sam + (size_t)b * Cn * Ln;
    float* At = g_attn + (size_t)b * Ln * Ln;

    // ---------------- Phase 0: simw; zero accumulators ----------------
    {
        const float* ib = imf + (size_t)b * Dn;
        const float* tb = txt + (size_t)b * Dn;
        float a0 = ib[t], c0 = tb[t];
        float ni = a0*a0, nt = c0*c0, ct = a0*c0;
        #pragma unroll
        for (int o = 16; o > 0; o >>= 1) {
            ni += __shfl_xor_sync(0xffffffffu, ni, o);
            nt += __shfl_xor_sync(0xffffffffu, nt, o);
            ct += __shfl_xor_sync(0xffffffffu, ct, o);
        }
        if (ln == 0) { red[0][w] = ni; red[1][w] = nt; red[2][w] = ct; }
        if (t < 200) { cs1[t] = 0.f; cs2[t] = 0.f; s_inv[t] = 0.f; }
        if (t < 208) s_rsum[t] = 0.f;
        __syncthreads();
        float nI = 0.f, nT = 0.f, cT = 0.f;
        #pragma unroll
        for (int j = 0; j < 16; j++) { nI += red[0][j]; nT += red[1][j]; cT += red[2][j]; }
        float invI = 1.0f / fmaxf(sqrtf(nI), 1e-12f);
        float invT = 1.0f / fmaxf(sqrtf(nT), 1e-12f);
        float cross = cT * invI * invT;
        s_im[t] = a0 * invI;
        __syncthreads();

        const float4* s4 = reinterpret_cast<const float4*>(s_im);
        for (int r = w; r < Ln; r += 16) {
            const float4* wr = reinterpret_cast<const float4*>(Wsim + (size_t)r * Dn);
            float acc = 0.f;
            #pragma unroll
            for (int i = 0; i < 4; i++) {
                float4 a = wr[ln + i * 32];
                float4 s = s4[ln + i * 32];
                acc += a.x*s.x + a.y*s.y + a.z*s.z + a.w*s.w;
            }
            #pragma unroll
            for (int o = 16; o > 0; o >>= 1) acc += __shfl_xor_sync(0xffffffffu, acc, o);
            if (ln == 0) {
                acc += bsim[r];
                s_simw[r] = cross * (1.0f / (1.0f + __expf(-acc))) * 0.1f;
            }
        }
    }
    __syncthreads();

    // ---------------- Phase 1: GEMM1 (bf16) -> raw exp -> g_attn -----------
    {
        uint32_t* Xw = reinterpret_cast<uint32_t*>(dyn);   // 208 x XWST bf16x2 words

        // column norms of sam (rows of X), direct from gmem
        if (t < 392) {
            int l = t >> 1, hf = t & 1;
            const float* p = Sb + (size_t)(hf * 128) * Ln + l;
            float s0 = 0.f, s1 = 0.f, s2 = 0.f, s3 = 0.f;
            #pragma unroll 4
            for (int c = 0; c < 128; c += 4) {
                float v0 = p[(c+0)*Ln], v1 = p[(c+1)*Ln];
                float v2 = p[(c+2)*Ln], v3 = p[(c+3)*Ln];
                s0 += v0*v0; s1 += v1*v1; s2 += v2*v2; s3 += v3*v3;
            }
            atomicAdd(&s_inv[l], (s0 + s1) + (s2 + s3));
        }
        // zero pad rows 196..207
        for (int i = t; i < 12 * XWST; i += 512) Xw[196 * XWST + i] = 0u;
        __syncthreads();
        if (t < Ln) s_inv[t] = 0.25f / fmaxf(sqrtf(s_inv[t]), 1e-12f);
        __syncthreads();

        // stage X as bf16, scaled, k(=c)-permuted: Xw[l][pword(c/2)] = {x(c), x(c+1)}
        for (int idx = t; idx < 128 * 49; idx += 512) {
            int c2 = idx / 49, l4 = idx % 49;
            int l0 = l4 * 4;
            float4 v0 = *reinterpret_cast<const float4*>(Sb + (size_t)(2*c2)   * Ln + l0);
            float4 v1 = *reinterpret_cast<const float4*>(Sb + (size_t)(2*c2+1) * Ln + l0);
            int wp = (c2 & ~7) + ((c2 & 3) << 1) + ((c2 >> 2) & 1);
            float i0 = s_inv[l0], i1 = s_inv[l0+1], i2 = s_inv[l0+2], i3 = s_inv[l0+3];
            __nv_bfloat162 h0 = __floats2bfloat162_rn(v0.x * i0, v1.x * i0);
            __nv_bfloat162 h1 = __floats2bfloat162_rn(v0.y * i1, v1.y * i1);
            __nv_bfloat162 h2 = __floats2bfloat162_rn(v0.z * i2, v1.z * i2);
            __nv_bfloat162 h3 = __floats2bfloat162_rn(v0.w * i3, v1.w * i3);
            Xw[(l0+0) * XWST + wp] = *reinterpret_cast<uint32_t*>(&h0);
            Xw[(l0+1) * XWST + wp] = *reinterpret_cast<uint32_t*>(&h1);
            Xw[(l0+2) * XWST + wp] = *reinterpret_cast<uint32_t*>(&h2);
            Xw[(l0+3) * XWST + wp] = *reinterpret_cast<uint32_t*>(&h3);
        }
        __syncthreads();

        // 52 jobs: (mt 0..12) x (quarter 0..3); widths 56/48/56/48
        for (int job = w; job < 52; job += 16) {
            int q = job & 3, mt = job >> 2;
            int cb = (q >> 1) * 104 + (q & 1) * 56;
            int wq = (q & 1) ? 48 : 56;

            float acc[7][4];
            #pragma unroll
            for (int n = 0; n < 7; n++)
                #pragma unroll
                for (int j = 0; j < 4; j++) acc[n][j] = 0.f;

            const uint32_t* A0 = Xw + (mt * 16 + g) * XWST + 2 * tig;
            const uint32_t* A1 = A0 + 8 * XWST;
            const uint32_t* Bb = Xw + (cb + g) * XWST + 2 * tig;
            #pragma unroll 4
            for (int ks = 0; ks < 16; ks++) {
                uint2 av0 = *reinterpret_cast<const uint2*>(A0 + ks * 8);
                uint2 av1 = *reinterpret_cast<const uint2*>(A1 + ks * 8);
                #pragma unroll
                for (int n = 0; n < 7; n++) {
                    if (n * 8 < wq) {
                        uint2 bv = *reinterpret_cast<const uint2*>(Bb + n * 8 * XWST + ks * 8);
                        mma16(acc[n], av0.x, av1.x, av0.y, av1.y, bv.x, bv.y);
                    }
                }
            }

            #pragma unroll
            for (int rh = 0; rh < 2; rh++) {
                int l = mt * 16 + g + 8 * rh;
                float sum = 0.f;
                #pragma unroll
                for (int n = 0; n < 7; n++) {
                    if (n * 8 < wq) {
                        int col0 = cb + n * 8 + 2 * tig;
                        float e0 = __expf(acc[n][rh*2]);
                        float e1 = __expf(acc[n][rh*2+1]);
                        acc[n][rh*2] = e0; acc[n][rh*2+1] = e1;
                        if (col0 < Ln) sum += e0 + e1;
                    }
                }
                sum += __shfl_xor_sync(0xffffffffu, sum, 1);
                sum += __shfl_xor_sync(0xffffffffu, sum, 2);
                if (l < Ln) {
                    if (tig == 0) atomicAdd(&s_rsum[l], sum);
                    float* ar = At + (size_t)l * Ln;
                    #pragma unroll
                    for (int n = 0; n < 7; n++) {
                        if (n * 8 < wq) {
                            int col0 = cb + n * 8 + 2 * tig;
                            if (col0 < Ln)
                                *reinterpret_cast<float2*>(ar + col0) =
                                    make_float2(acc[n][rh*2], acc[n][rh*2+1]);
                        }
                    }
                }
            }
        }
    }
    __syncthreads();
    if (t < Ln) s_rsum[t] = 1.0f / s_rsum[t];
    __syncthreads();

    // ---------------- Phase 2: GEMM2 (tf32); y -> out; column stats ----------
    {
        float* B_sm = dyn;                   // 200 x BST
        float* A_sm = dyn + 200 * BST;       // 256 x AST

        // stage B[m][perm(l)] = exp[m][l] (symmetry!) / rsum[l], tf32
        for (int idx = t; idx < 200 * 50; idx += 512) {
            int m = idx / 50, ch = idx % 50;
            int l0 = ch * 4;
            float4 v = make_float4(0.f, 0.f, 0.f, 0.f);
            if (m < Ln && ch < 49) {
                v = *reinterpret_cast<const float4*>(At + (size_t)m * Ln + l0);
                v.x *= s_rsum[l0]; v.y *= s_rsum[l0+1];
                v.z *= s_rsum[l0+2]; v.w *= s_rsum[l0+3];
            }
            float* dst = B_sm + m * BST;
            dst[pidx(l0)]   = __uint_as_float(f2tf(v.x));
            dst[pidx(l0+1)] = __uint_as_float(f2tf(v.y));
            dst[pidx(l0+2)] = __uint_as_float(f2tf(v.z));
            dst[pidx(l0+3)] = __uint_as_float(f2tf(v.w));
        }

        #pragma unroll
        for (int h = 0; h < 2; h++) {
            int cbm = h * 104;
            float acc[13][4];
            #pragma unroll
            for (int n = 0; n < 13; n++)
                #pragma unroll
                for (int j = 0; j < 4; j++) acc[n][j] = 0.f;

            for (int p = 0; p < 5; p++) {
                __syncthreads();
                // stage A panel: A[c][perm(local l)], tf32
                for (int idx = t; idx < 256 * 10; idx += 512) {
                    int cr = idx / 10, ch = idx % 10;
                    int gk = p * 40 + ch * 4;
                    float4 v = make_float4(0.f, 0.f, 0.f, 0.f);
                    if (gk < Ln) v = *reinterpret_cast<const float4*>(Sb + (size_t)cr * Ln + gk);
                    float* dst = A_sm + cr * AST;
                    int lo = ch * 4;
                    dst[pidx(lo)]   = __uint_as_float(f2tf(v.x));
                    dst[pidx(lo+1)] = __uint_as_float(f2tf(v.y));
                    dst[pidx(lo+2)] = __uint_as_float(f2tf(v.z));
                    dst[pidx(lo+3)] = __uint_as_float(f2tf(v.w));
                }
                __syncthreads();

                const float* A0 = A_sm + (w * 16 + g) * AST + 2 * tig;
                const float* A1 = A0 + 8 * AST;
                #pragma unroll
                for (int ks = 0; ks < 5; ks++) {
                    int kg = p * 5 + ks;
                    float2 av0 = *reinterpret_cast<const float2*>(A0 + ks * 8);
                    float2 av1 = *reinterpret_cast<const float2*>(A1 + ks * 8);
                    const float* Bb = B_sm + (cbm + g) * BST + kg * 8 + 2 * tig;
                    #pragma unroll
                    for (int n = 0; n < 13; n++) {
                        if (cbm + n * 8 < 200) {
                            float2 bv = *reinterpret_cast<const float2*>(Bb + n * 8 * BST);
                            mma8(acc[n], fu(av0.x), fu(av1.x), fu(av0.y), fu(av1.y),
                                 fu(bv.x), fu(bv.y));
                        }
                    }
                }
            }

            // epilogue: y = sam + D -> out; column stats
            int c0r = w * 16 + g;
            int c1r = c0r + 8;
            const float* S0 = Sb + (size_t)c0r * Ln;
            const float* S1 = Sb + (size_t)c1r * Ln;
            float* O0 = out + ((size_t)b * Cn + c0r) * Ln;
            float* O1 = out + ((size_t)b * Cn + c1r) * Ln;
            #pragma unroll
            for (int n = 0; n < 13; n++) {
                if (cbm + n * 8 < 200) {
                    int col0 = cbm + n * 8 + 2 * tig;
                    bool v = col0 < Ln;
                    float y0 = 0.f, y1 = 0.f, y2 = 0.f, y3 = 0.f;
                    if (v) {
                        float2 s0 = *reinterpret_cast<const float2*>(S0 + col0);
                        float2 s1 = *reinterpret_cast<const float2*>(S1 + col0);
                        y0 = s0.x + acc[n][0]; y1 = s0.y + acc[n][1];
                        y2 = s1.x + acc[n][2]; y3 = s1.y + acc[n][3];
                        *reinterpret_cast<float2*>(O0 + col0) = make_float2(y0, y1);
                        *reinterpret_cast<float2*>(O1 + col0) = make_float2(y2, y3);
                    }
                    float sa0 = y0 + y2, sa1 = y1 + y3;
                    float sq0 = y0*y0 + y2*y2, sq1 = y1*y1 + y3*y3;
                    #pragma unroll
                    for (int o = 4; o < 32; o <<= 1) {
                        sa0 += __shfl_xor_sync(0xffffffffu, sa0, o);
                        sa1 += __shfl_xor_sync(0xffffffffu, sa1, o);
                        sq0 += __shfl_xor_sync(0xffffffffu, sq0, o);
                        sq1 += __shfl_xor_sync(0xffffffffu, sq1, o);
                    }
                    if (g == 0 && v) {
                        atomicAdd(&cs1[col0], sa0);     atomicAdd(&cs1[col0 + 1], sa1);
                        atomicAdd(&cs2[col0], sq0);     atomicAdd(&cs2[col0 + 1], sq1);
                    }
                }
            }
        }
    }
    __syncthreads();

    // ---------------- Phase 3: channel-LN affine P,Q ----------------
    if (t < Ln) {
        float a = 0.5f * s_simw[t];
        float mu_y  = cs1[t] * (1.0f / Cn);
        float var_y = cs2[t] * (1.0f / Cn) - mu_y * mu_y;
        float inv_s = rsqrtf(a * a * var_y + 1e-5f);
        cs1[t] = a * inv_s;
        cs2[t] = -a * mu_y * inv_s;
    }
    if (t >= Ln && t < 200) { cs1[t] = 0.f; cs2[t] = 0.f; }
    __syncthreads();

    // ---------------- Phase 4: spatial standardization (out L2-hot) ----------
    {
        const float4* P4 = reinterpret_cast<const float4*>(cs1);
        const float4* Q4 = reinterpret_cast<const float4*>(cs2);
        bool has2 = (ln + 32) < Ln / 4;
        int g2 = has2 ? (ln + 32) : 0;
        float4 p0 = P4[ln], q0 = Q4[ln];
        float4 p1 = P4[g2], q1 = Q4[g2];

        for (int c = w; c < Cn; c += 16) {
            float4* orow = reinterpret_cast<float4*>(out + ((size_t)b * Cn + c) * Ln);
            float4 y0 = orow[ln];
            float x0[4] = { fmaf(y0.x, p0.x, q0.x), fmaf(y0.y, p0.y, q0.y),
                            fmaf(y0.z, p0.z, q0.z), fmaf(y0.w, p0.w, q0.w) };
            float x1[4] = { 0.f, 0.f, 0.f, 0.f };
            if (has2) {
                float4 y1 = orow[g2];
                x1[0] = fmaf(y1.x, p1.x, q1.x); x1[1] = fmaf(y1.y, p1.y, q1.y);
                x1[2] = fmaf(y1.z, p1.z, q1.z); x1[3] = fmaf(y1.w, p1.w, q1.w);
            }
            float s1 = x0[0] + x0[1] + x0[2] + x0[3];
            float s2 = x0[0]*x0[0] + x0[1]*x0[1] + x0[2]*x0[2] + x0[3]*x0[3];
            if (has2) {
                s1 += x1[0] + x1[1] + x1[2] + x1[3];
                s2 += x1[0]*x1[0] + x1[1]*x1[1] + x1[2]*x1[2] + x1[3]*x1[3];
            }
            #pragma unroll
            for (int o = 16; o > 0; o >>= 1) {
                s1 += __shfl_xor_sync(0xffffffffu, s1, o);
                s2 += __shfl_xor_sync(0xffffffffu, s2, o);
            }
            float mean = s1 * (1.0f / Ln);
            float var  = (s2 - (float)Ln * mean * mean) * (1.0f / (Ln - 1));
            float inv  = 1.0f / (sqrtf(fmaxf(var, 0.f)) + 1e-6f);

            float4 o0 = { (x0[0]-mean)*inv, (x0[1]-mean)*inv, (x0[2]-mean)*inv, (x0[3]-mean)*inv };
            orow[ln] = o0;
            if (has2) {
                float4 o1 = { (x1[0]-mean)*inv, (x1[1]-mean)*inv, (x1[2]-mean)*inv, (x1[3]-mean)*inv };
                orow[g2] = o1;
            }
        }
    }
}

// ============================================================================
extern "C" void kernel_launch(void* const* d_in, const int* in_sizes, int n_in,
                              void* d_out, int out_size)
{
    const float* imf  = (const float*)d_in[0];
    const float* txt  = (const float*)d_in[1];
    const float* sam  = (const float*)d_in[2];
    const float* Wsim = (const float*)d_in[3];
    const float* bsim = (const float*)d_in[4];
    float* out = (float*)d_out;

    // max(phase1: 208*136*4 = 113,152 ; phase2: (200*200 + 256*40)*4 = 200,960)
    const int smem = 200960;
    cudaFuncSetAttribute(k_main, cudaFuncAttributeMaxDynamicSharedMemorySize, smem);
    k_main<<<Bn, 512, smem>>>(imf, txt, sam, Wsim, bsim, out);
}

// round 9
// speedup vs baseline: 1.2663x; 1.0514x over previous
#include <cuda_runtime.h>
#include <cuda_bf16.h>
#include <math.h>
#include <stdint.h>

#define Bn 512
#define Cn 256
#define Ln 196
#define Dn 512
#define XWST 136   // Xt word stride (uint32): 68 8B-units ≡ 4 mod 16 -> 2-way floor
#define BST  200   // B_sm float stride
#define AST  40    // A_sm float stride

#define NT 1024    // threads per CTA (32 warps)

// raw exp scratch (SYMMETRIC matrix; same-CTA reuse -> L2-resident)
static __device__ float g_attn[(size_t)Bn * Ln * Ln];

__device__ __forceinline__ uint32_t f2tf(float f) {
    uint32_t r;
    asm("cvt.rna.tf32.f32 %0, %1;" : "=r"(r) : "f"(f));
    return r;
}
__device__ __forceinline__ uint32_t fu(float f) { return __float_as_uint(f); }
__device__ __forceinline__ int pidx(int l) {    // k-perm: (k=tig, k=tig+4) adjacent
    return (l & ~7) + ((l & 3) << 1) + ((l >> 2) & 1);
}

__device__ __forceinline__ void mma8(float* d, uint32_t a0, uint32_t a1, uint32_t a2,
                                     uint32_t a3, uint32_t b0, uint32_t b1) {
    asm volatile("mma.sync.aligned.m16n8k8.row.col.f32.tf32.tf32.f32 "
        "{%0,%1,%2,%3}, {%4,%5,%6,%7}, {%8,%9}, {%0,%1,%2,%3};"
        : "+f"(d[0]), "+f"(d[1]), "+f"(d[2]), "+f"(d[3])
        : "r"(a0), "r"(a1), "r"(a2), "r"(a3), "r"(b0), "r"(b1));
}
__device__ __forceinline__ void mma16(float* d, uint32_t a0, uint32_t a1, uint32_t a2,
                                      uint32_t a3, uint32_t b0, uint32_t b1) {
    asm volatile("mma.sync.aligned.m16n8k16.row.col.f32.bf16.bf16.f32 "
        "{%0,%1,%2,%3}, {%4,%5,%6,%7}, {%8,%9}, {%0,%1,%2,%3};"
        : "+f"(d[0]), "+f"(d[1]), "+f"(d[2]), "+f"(d[3])
        : "r"(a0), "r"(a1), "r"(a2), "r"(a3), "r"(b0), "r"(b1));
}

// ============================================================================
// Mega-kernel: one CTA per batch, 1024 threads (32 warps), <=64 regs/thread.
// ============================================================================
__global__ __launch_bounds__(NT, 1) void k_main(
    const float* __restrict__ imf, const float* __restrict__ txt,
    const float* __restrict__ sam, const float* __restrict__ Wsim,
    const float* __restrict__ bsim, float* __restrict__ out)
{
    extern __shared__ float dyn[];          // 200,960 B
    __shared__ float s_im[Dn];
    __shared__ float red[3][32];
    __shared__ float s_simw[200];
    __shared__ __align__(16) float cs1[200];
    __shared__ __align__(16) float cs2[200];
    __shared__ float s_rsum[208];
    __shared__ float s_inv[256];

    int b = blockIdx.x, t = threadIdx.x, w = t >> 5, ln = t & 31;
    int g = ln >> 2, tig = ln & 3;
    const float* Sb = sam + (size_t)b * Cn * Ln;
    float* At = g_attn + (size_t)b * Ln * Ln;

    // ---------------- Phase 0: simw; zero accumulators ----------------
    {
        float a0 = 0.f, c0 = 0.f;
        if (t < Dn) {
            a0 = imf[(size_t)b * Dn + t];
            c0 = txt[(size_t)b * Dn + t];
        }
        float ni = a0*a0, nt = c0*c0, ct = a0*c0;
        #pragma unroll
        for (int o = 16; o > 0; o >>= 1) {
            ni += __shfl_xor_sync(0xffffffffu, ni, o);
            nt += __shfl_xor_sync(0xffffffffu, nt, o);
            ct += __shfl_xor_sync(0xffffffffu, ct, o);
        }
        if (ln == 0) { red[0][w] = ni; red[1][w] = nt; red[2][w] = ct; }
        if (t < 200) { cs1[t] = 0.f; cs2[t] = 0.f; }
        if (t < 256) s_inv[t] = 0.f;
        if (t >= 256 && t < 464) s_rsum[t - 256] = 0.f;
        __syncthreads();
        float nI = 0.f, nT = 0.f, cT = 0.f;
        #pragma unroll
        for (int j = 0; j < 32; j++) { nI += red[0][j]; nT += red[1][j]; cT += red[2][j]; }
        float invI = 1.0f / fmaxf(sqrtf(nI), 1e-12f);
        float invT = 1.0f / fmaxf(sqrtf(nT), 1e-12f);
        float cross = cT * invI * invT;
        if (t < Dn) s_im[t] = imf[(size_t)b * Dn + t] * invI;
        __syncthreads();

        const float4* s4 = reinterpret_cast<const float4*>(s_im);
        for (int r = w; r < Ln; r += 32) {
            const float4* wr = reinterpret_cast<const float4*>(Wsim + (size_t)r * Dn);
            float acc = 0.f;
            #pragma unroll
            for (int i = 0; i < 4; i++) {
                float4 a = wr[ln + i * 32];
                float4 s = s4[ln + i * 32];
                acc += a.x*s.x + a.y*s.y + a.z*s.z + a.w*s.w;
            }
            #pragma unroll
            for (int o = 16; o > 0; o >>= 1) acc += __shfl_xor_sync(0xffffffffu, acc, o);
            if (ln == 0) {
                acc += bsim[r];
                s_simw[r] = cross * (1.0f / (1.0f + __expf(-acc))) * 0.1f;
            }
        }
    }
    __syncthreads();

    // ---------------- Phase 1: GEMM1 (bf16) -> raw exp -> g_attn -----------
    {
        uint32_t* Xw = reinterpret_cast<uint32_t*>(dyn);   // 208 x XWST bf16x2

        // column norms, COALESCED: thread -> column l = t&255, chunk = t>>8 (64 c each)
        {
            int l = t & 255, ch = t >> 8;
            if (l < Ln) {
                const float* p = Sb + (size_t)(ch * 64) * Ln + l;
                float s0 = 0.f, s1 = 0.f;
                #pragma unroll 8
                for (int c = 0; c < 64; c += 2) {
                    float v0 = p[c * Ln], v1 = p[(c + 1) * Ln];
                    s0 += v0 * v0; s1 += v1 * v1;
                }
                atomicAdd(&s_inv[l], s0 + s1);
            }
        }
        // zero pad rows 196..207
        for (int i = t; i < 12 * XWST; i += NT) Xw[196 * XWST + i] = 0u;
        __syncthreads();
        if (t < Ln) s_inv[t] = 0.25f / fmaxf(sqrtf(s_inv[t]), 1e-12f);
        __syncthreads();

        // stage X as bf16, scaled, c-word-permuted
        for (int idx = t; idx < 128 * 49; idx += NT) {
            int c2 = idx / 49, l4 = idx % 49;
            int l0 = l4 * 4;
            float4 v0 = *reinterpret_cast<const float4*>(Sb + (size_t)(2*c2)   * Ln + l0);
            float4 v1 = *reinterpret_cast<const float4*>(Sb + (size_t)(2*c2+1) * Ln + l0);
            int wp = (c2 & ~7) + ((c2 & 3) << 1) + ((c2 >> 2) & 1);
            float i0 = s_inv[l0], i1 = s_inv[l0+1], i2 = s_inv[l0+2], i3 = s_inv[l0+3];
            __nv_bfloat162 h0 = __floats2bfloat162_rn(v0.x * i0, v1.x * i0);
            __nv_bfloat162 h1 = __floats2bfloat162_rn(v0.y * i1, v1.y * i1);
            __nv_bfloat162 h2 = __floats2bfloat162_rn(v0.z * i2, v1.z * i2);
            __nv_bfloat162 h3 = __floats2bfloat162_rn(v0.w * i3, v1.w * i3);
            Xw[(l0+0) * XWST + wp] = *reinterpret_cast<uint32_t*>(&h0);
            Xw[(l0+1) * XWST + wp] = *reinterpret_cast<uint32_t*>(&h1);
            Xw[(l0+2) * XWST + wp] = *reinterpret_cast<uint32_t*>(&h2);
            Xw[(l0+3) * XWST + wp] = *reinterpret_cast<uint32_t*>(&h3);
        }
        __syncthreads();

        // 65 jobs: (mt 0..12) x (slice 0..4 of 40 cols)
        for (int job = w; job < 65; job += 32) {
            int mt = job / 5, sl = job % 5;
            int cb = sl * 40;

            float acc[5][4];
            #pragma unroll
            for (int n = 0; n < 5; n++)
                #pragma unroll
                for (int j = 0; j < 4; j++) acc[n][j] = 0.f;

            const uint32_t* A0 = Xw + (mt * 16 + g) * XWST + 2 * tig;
            const uint32_t* A1 = A0 + 8 * XWST;
            const uint32_t* Bb = Xw + (cb + g) * XWST + 2 * tig;
            #pragma unroll 4
            for (int ks = 0; ks < 16; ks++) {
                uint2 av0 = *reinterpret_cast<const uint2*>(A0 + ks * 8);
                uint2 av1 = *reinterpret_cast<const uint2*>(A1 + ks * 8);
                #pragma unroll
                for (int n = 0; n < 5; n++) {
                    uint2 bv = *reinterpret_cast<const uint2*>(Bb + n * 8 * XWST + ks * 8);
                    mma16(acc[n], av0.x, av1.x, av0.y, av1.y, bv.x, bv.y);
                }
            }

            #pragma unroll
            for (int rh = 0; rh < 2; rh++) {
                int l = mt * 16 + g + 8 * rh;
                float sum = 0.f;
                #pragma unroll
                for (int n = 0; n < 5; n++) {
                    int col0 = cb + n * 8 + 2 * tig;
                    float e0 = __expf(acc[n][rh*2]);
                    float e1 = __expf(acc[n][rh*2+1]);
                    acc[n][rh*2] = e0; acc[n][rh*2+1] = e1;
                    if (col0 < Ln) sum += e0 + e1;
                }
                sum += __shfl_xor_sync(0xffffffffu, sum, 1);
                sum += __shfl_xor_sync(0xffffffffu, sum, 2);
                if (l < Ln) {
                    if (tig == 0) atomicAdd(&s_rsum[l], sum);
                    float* ar = At + (size_t)l * Ln;
                    #pragma unroll
                    for (int n = 0; n < 5; n++) {
                        int col0 = cb + n * 8 + 2 * tig;
                        if (col0 < Ln)
                            *reinterpret_cast<float2*>(ar + col0) =
                                make_float2(acc[n][rh*2], acc[n][rh*2+1]);
                    }
                }
            }
        }
    }
    __syncthreads();
    if (t < Ln) s_rsum[t] = 1.0f / s_rsum[t];
    __syncthreads();

    // ---------------- Phase 2: GEMM2 (tf32); y -> out; column stats ----------
    {
        float* B_sm = dyn;                   // 200 x BST
        float* A_sm = dyn + 200 * BST;       // 256 x AST

        // stage B[m][perm(l)] = exp[m][l] (symmetry) / rsum[l], tf32
        for (int idx = t; idx < 200 * 50; idx += NT) {
            int m = idx / 50, ch = idx % 50;
            int l0 = ch * 4;
            float4 v = make_float4(0.f, 0.f, 0.f, 0.f);
            if (m < Ln && ch < 49) {
                v = *reinterpret_cast<const float4*>(At + (size_t)m * Ln + l0);
                v.x *= s_rsum[l0]; v.y *= s_rsum[l0+1];
                v.z *= s_rsum[l0+2]; v.w *= s_rsum[l0+3];
            }
            float* dst = B_sm + m * BST;
            dst[pidx(l0)]   = __uint_as_float(f2tf(v.x));
            dst[pidx(l0+1)] = __uint_as_float(f2tf(v.y));
            dst[pidx(l0+2)] = __uint_as_float(f2tf(v.z));
            dst[pidx(l0+3)] = __uint_as_float(f2tf(v.w));
        }

        // 64 jobs: (mt 0..15) x (quarter 0..3); cb {0,56,104,160}, nfr {7,6,7,5}
        #pragma unroll
        for (int r = 0; r < 2; r++) {
            int job = w + r * 32;
            int mt = job >> 2, q = job & 3;
            int cbm = (q == 0) ? 0 : (q == 1) ? 56 : (q == 2) ? 104 : 160;
            int nfr = (q == 0 || q == 2) ? 7 : (q == 1) ? 6 : 5;

            float acc[7][4];
            #pragma unroll
            for (int n = 0; n < 7; n++)
                #pragma unroll
                for (int j = 0; j < 4; j++) acc[n][j] = 0.f;

            for (int p = 0; p < 5; p++) {
                __syncthreads();
                // stage A panel: A[c][perm(local l)], tf32 (all 256 rows x 40 k)
                for (int idx = t; idx < 256 * 10; idx += NT) {
                    int cr = idx / 10, ch = idx % 10;
                    int gk = p * 40 + ch * 4;
                    float4 v = make_float4(0.f, 0.f, 0.f, 0.f);
                    if (gk < Ln) v = *reinterpret_cast<const float4*>(Sb + (size_t)cr * Ln + gk);
                    float* dst = A_sm + cr * AST;
                    int lo = ch * 4;
                    dst[pidx(lo)]   = __uint_as_float(f2tf(v.x));
                    dst[pidx(lo+1)] = __uint_as_float(f2tf(v.y));
                    dst[pidx(lo+2)] = __uint_as_float(f2tf(v.z));
                    dst[pidx(lo+3)] = __uint_as_float(f2tf(v.w));
                }
                __syncthreads();

                const float* A0 = A_sm + (mt * 16 + g) * AST + 2 * tig;
                const float* A1 = A0 + 8 * AST;
                #pragma unroll
                for (int ks = 0; ks < 5; ks++) {
                    int kg = p * 5 + ks;
                    float2 av0 = *reinterpret_cast<const float2*>(A0 + ks * 8);
                    float2 av1 = *reinterpret_cast<const float2*>(A1 + ks * 8);
                    const float* Bb = B_sm + (cbm + g) * BST + kg * 8 + 2 * tig;
                    #pragma unroll
                    for (int n = 0; n < 7; n++) {
                        if (n < nfr) {
                            float2 bv = *reinterpret_cast<const float2*>(Bb + n * 8 * BST);
                            mma8(acc[n], fu(av0.x), fu(av1.x), fu(av0.y), fu(av1.y),
                                 fu(bv.x), fu(bv.y));
                        }
                    }
                }
            }

            // epilogue: y = sam + D -> out; column stats
            int c0r = mt * 16 + g;
            int c1r = c0r + 8;
            const float* S0 = Sb + (size_t)c0r * Ln;
            const float* S1 = Sb + (size_t)c1r * Ln;
            float* O0 = out + ((size_t)b * Cn + c0r) * Ln;
            float* O1 = out + ((size_t)b * Cn + c1r) * Ln;
            #pragma unroll
            for (int n = 0; n < 7; n++) {
                if (n < nfr) {
                    int col0 = cbm + n * 8 + 2 * tig;
                    bool v = col0 < Ln;
                    float y0 = 0.f, y1 = 0.f, y2 = 0.f, y3 = 0.f;
                    if (v) {
                        float2 s0 = *reinterpret_cast<const float2*>(S0 + col0);
                        float2 s1 = *reinterpret_cast<const float2*>(S1 + col0);
                        y0 = s0.x + acc[n][0]; y1 = s0.y + acc[n][1];
                        y2 = s1.x + acc[n][2]; y3 = s1.y + acc[n][3];
                        *reinterpret_cast<float2*>(O0 + col0) = make_float2(y0, y1);
                        *reinterpret_cast<float2*>(O1 + col0) = make_float2(y2, y3);
                    }
                    float sa0 = y0 + y2, sa1 = y1 + y3;
                    float sq0 = y0*y0 + y2*y2, sq1 = y1*y1 + y3*y3;
                    #pragma unroll
                    for (int o = 4; o < 32; o <<= 1) {
                        sa0 += __shfl_xor_sync(0xffffffffu, sa0, o);
                        sa1 += __shfl_xor_sync(0xffffffffu, sa1, o);
                        sq0 += __shfl_xor_sync(0xffffffffu, sq0, o);
                        sq1 += __shfl_xor_sync(0xffffffffu, sq1, o);
                    }
                    if (g == 0 && v) {
                        atomicAdd(&cs1[col0], sa0);     atomicAdd(&cs1[col0 + 1], sa1);
                        atomicAdd(&cs2[col0], sq0);     atomicAdd(&cs2[col0 + 1], sq1);
                    }
                }
            }
        }
    }
    __syncthreads();

    // ---------------- Phase 3: channel-LN affine P,Q ----------------
    if (t < Ln) {
        float a = 0.5f * s_simw[t];
        float mu_y  = cs1[t] * (1.0f / Cn);
        float var_y = cs2[t] * (1.0f / Cn) - mu_y * mu_y;
        float inv_s = rsqrtf(a * a * var_y + 1e-5f);
        cs1[t] = a * inv_s;
        cs2[t] = -a * mu_y * inv_s;
    }
    if (t >= Ln && t < 200) { cs1[t] = 0.f; cs2[t] = 0.f; }
    __syncthreads();

    // ---------------- Phase 4: spatial standardization (out L2-hot) ----------
    {
        const float4* P4 = reinterpret_cast<const float4*>(cs1);
        const float4* Q4 = reinterpret_cast<const float4*>(cs2);
        bool has2 = (ln + 32) < Ln / 4;
        int g2 = has2 ? (ln + 32) : 0;
        float4 p0 = P4[ln], q0 = Q4[ln];
        float4 p1 = P4[g2], q1 = Q4[g2];

        for (int c = w; c < Cn; c += 32) {
            float4* orow = reinterpret_cast<float4*>(out + ((size_t)b * Cn + c) * Ln);
            float4 y0 = orow[ln];
            float x0[4] = { fmaf(y0.x, p0.x, q0.x), fmaf(y0.y, p0.y, q0.y),
                            fmaf(y0.z, p0.z, q0.z), fmaf(y0.w, p0.w, q0.w) };
            float x1[4] = { 0.f, 0.f, 0.f, 0.f };
            if (has2) {
                float4 y1 = orow[g2];
                x1[0] = fmaf(y1.x, p1.x, q1.x); x1[1] = fmaf(y1.y, p1.y, q1.y);
                x1[2] = fmaf(y1.z, p1.z, q1.z); x1[3] = fmaf(y1.w, p1.w, q1.w);
            }
            float s1 = x0[0] + x0[1] + x0[2] + x0[3];
            float s2 = x0[0]*x0[0] + x0[1]*x0[1] + x0[2]*x0[2] + x0[3]*x0[3];
            if (has2) {
                s1 += x1[0] + x1[1] + x1[2] + x1[3];
                s2 += x1[0]*x1[0] + x1[1]*x1[1] + x1[2]*x1[2] + x1[3]*x1[3];
            }
            #pragma unroll
            for (int o = 16; o > 0; o >>= 1) {
                s1 += __shfl_xor_sync(0xffffffffu, s1, o);
                s2 += __shfl_xor_sync(0xffffffffu, s2, o);
            }
            float mean = s1 * (1.0f / Ln);
            float var  = (s2 - (float)Ln * mean * mean) * (1.0f / (Ln - 1));
            float inv  = 1.0f / (sqrtf(fmaxf(var, 0.f)) + 1e-6f);

            float4 o0 = { (x0[0]-mean)*inv, (x0[1]-mean)*inv, (x0[2]-mean)*inv, (x0[3]-mean)*inv };
            orow[ln] = o0;
            if (has2) {
                float4 o1 = { (x1[0]-mean)*inv, (x1[1]-mean)*inv, (x1[2]-mean)*inv, (x1[3]-mean)*inv };
                orow[g2] = o1;
            }
        }
    }
}

// ============================================================================
extern "C" void kernel_launch(void* const* d_in, const int* in_sizes, int n_in,
                              void* d_out, int out_size)
{
    const float* imf  = (const float*)d_in[0];
    const float* txt  = (const float*)d_in[1];
    const float* sam  = (const float*)d_in[2];
    const float* Wsim = (const float*)d_in[3];
    const float* bsim = (const float*)d_in[4];
    float* out = (float*)d_out;

    // max(phase1: 208*136*4 = 113,152 ; phase2: (200*200 + 256*40)*4 = 200,960)
    const int smem = 200960;
    cudaFuncSetAttribute(k_main, cudaFuncAttributeMaxDynamicSharedMemorySize, smem);
    k_main<<<Bn, NT, smem>>>(imf, txt, sam, Wsim, bsim, out);
}

// round 10
// speedup vs baseline: 1.6227x; 1.2814x over previous
#include <cuda_runtime.h>
#include <cuda_bf16.h>
#include <math.h>
#include <stdint.h>

#define Bn 512
#define Cn 256
#define Ln 196
#define Dn 512
#define XWST 136   // phase-1 Xt word stride: 68 8B-units ≡ 4 mod 16 -> 2-way floor
#define WST2 104   // phase-2 A/B word stride: 52 8B-units ≡ 4 mod 16 -> same floor

#define NT 1024    // threads per CTA (32 warps)

// raw exp scratch (SYMMETRIC matrix; same-CTA reuse -> L2-resident)
static __device__ float g_attn[(size_t)Bn * Ln * Ln];

__device__ __forceinline__ uint32_t fu(float f) { return __float_as_uint(f); }
__device__ __forceinline__ int pw8(int w2) {    // word-perm: (word tig, tig+4) adjacent
    return (w2 & ~7) + ((w2 & 3) << 1) + ((w2 >> 2) & 1);
}

__device__ __forceinline__ void mma16(float* d, uint32_t a0, uint32_t a1, uint32_t a2,
                                      uint32_t a3, uint32_t b0, uint32_t b1) {
    asm volatile("mma.sync.aligned.m16n8k16.row.col.f32.bf16.bf16.f32 "
        "{%0,%1,%2,%3}, {%4,%5,%6,%7}, {%8,%9}, {%0,%1,%2,%3};"
        : "+f"(d[0]), "+f"(d[1]), "+f"(d[2]), "+f"(d[3])
        : "r"(a0), "r"(a1), "r"(a2), "r"(a3), "r"(b0), "r"(b1));
}

// ============================================================================
// Mega-kernel: one CTA per batch, 1024 threads (32 warps).
// ============================================================================
__global__ __launch_bounds__(NT, 1) void k_main(
    const float* __restrict__ imf, const float* __restrict__ txt,
    const float* __restrict__ sam, const float* __restrict__ Wsim,
    const float* __restrict__ bsim, float* __restrict__ out)
{
    extern __shared__ float dyn[];          // 189,696 B
    __shared__ float s_im[Dn];
    __shared__ float red[3][32];
    __shared__ float s_simw[200];
    __shared__ __align__(16) float cs1[200];
    __shared__ __align__(16) float cs2[200];
    __shared__ float s_rsum[208];
    __shared__ float s_inv[256];

    int b = blockIdx.x, t = threadIdx.x, w = t >> 5, ln = t & 31;
    int g = ln >> 2, tig = ln & 3;
    const float* Sb = sam + (size_t)b * Cn * Ln;
    float* At = g_attn + (size_t)b * Ln * Ln;

    // ---------------- Phase 0: simw; zero accumulators ----------------
    {
        float a0 = 0.f, c0 = 0.f;
        if (t < Dn) {
            a0 = imf[(size_t)b * Dn + t];
            c0 = txt[(size_t)b * Dn + t];
        }
        float ni = a0*a0, nt = c0*c0, ct = a0*c0;
        #pragma unroll
        for (int o = 16; o > 0; o >>= 1) {
            ni += __shfl_xor_sync(0xffffffffu, ni, o);
            nt += __shfl_xor_sync(0xffffffffu, nt, o);
            ct += __shfl_xor_sync(0xffffffffu, ct, o);
        }
        if (ln == 0) { red[0][w] = ni; red[1][w] = nt; red[2][w] = ct; }
        if (t < 200) { cs1[t] = 0.f; cs2[t] = 0.f; }
        if (t < 256) s_inv[t] = 0.f;
        if (t >= 256 && t < 464) s_rsum[t - 256] = 0.f;
        __syncthreads();
        float nI = 0.f, nT = 0.f, cT = 0.f;
        #pragma unroll
        for (int j = 0; j < 32; j++) { nI += red[0][j]; nT += red[1][j]; cT += red[2][j]; }
        float invI = 1.0f / fmaxf(sqrtf(nI), 1e-12f);
        float invT = 1.0f / fmaxf(sqrtf(nT), 1e-12f);
        float cross = cT * invI * invT;
        if (t < Dn) s_im[t] = imf[(size_t)b * Dn + t] * invI;
        __syncthreads();

        const float4* s4 = reinterpret_cast<const float4*>(s_im);
        for (int r = w; r < Ln; r += 32) {
            const float4* wr = reinterpret_cast<const float4*>(Wsim + (size_t)r * Dn);
            float acc = 0.f;
            #pragma unroll
            for (int i = 0; i < 4; i++) {
                float4 a = wr[ln + i * 32];
                float4 s = s4[ln + i * 32];
                acc += a.x*s.x + a.y*s.y + a.z*s.z + a.w*s.w;
            }
            #pragma unroll
            for (int o = 16; o > 0; o >>= 1) acc += __shfl_xor_sync(0xffffffffu, acc, o);
            if (ln == 0) {
                acc += bsim[r];
                s_simw[r] = cross * (1.0f / (1.0f + __expf(-acc))) * 0.1f;
            }
        }
    }
    __syncthreads();

    // ---------------- Phase 1: GEMM1 (bf16) -> raw exp -> g_attn -----------
    {
        uint32_t* Xw = reinterpret_cast<uint32_t*>(dyn);   // 208 x XWST bf16x2

        // column norms, coalesced: thread -> column l = t&255, chunk = t>>8
        {
            int l = t & 255, ch = t >> 8;
            if (l < Ln) {
                const float* p = Sb + (size_t)(ch * 64) * Ln + l;
                float s0 = 0.f, s1 = 0.f;
                #pragma unroll 8
                for (int c = 0; c < 64; c += 2) {
                    float v0 = p[c * Ln], v1 = p[(c + 1) * Ln];
                    s0 += v0 * v0; s1 += v1 * v1;
                }
                atomicAdd(&s_inv[l], s0 + s1);
            }
        }
        for (int i = t; i < 12 * XWST; i += NT) Xw[196 * XWST + i] = 0u;
        __syncthreads();
        if (t < Ln) s_inv[t] = 0.25f / fmaxf(sqrtf(s_inv[t]), 1e-12f);
        __syncthreads();

        // stage X as bf16, scaled, c-word-permuted
        for (int idx = t; idx < 128 * 49; idx += NT) {
            int c2 = idx / 49, l4 = idx % 49;
            int l0 = l4 * 4;
            float4 v0 = *reinterpret_cast<const float4*>(Sb + (size_t)(2*c2)   * Ln + l0);
            float4 v1 = *reinterpret_cast<const float4*>(Sb + (size_t)(2*c2+1) * Ln + l0);
            int wp = pw8(c2);
            float i0 = s_inv[l0], i1 = s_inv[l0+1], i2 = s_inv[l0+2], i3 = s_inv[l0+3];
            __nv_bfloat162 h0 = __floats2bfloat162_rn(v0.x * i0, v1.x * i0);
            __nv_bfloat162 h1 = __floats2bfloat162_rn(v0.y * i1, v1.y * i1);
            __nv_bfloat162 h2 = __floats2bfloat162_rn(v0.z * i2, v1.z * i2);
            __nv_bfloat162 h3 = __floats2bfloat162_rn(v0.w * i3, v1.w * i3);
            Xw[(l0+0) * XWST + wp] = *reinterpret_cast<uint32_t*>(&h0);
            Xw[(l0+1) * XWST + wp] = *reinterpret_cast<uint32_t*>(&h1);
            Xw[(l0+2) * XWST + wp] = *reinterpret_cast<uint32_t*>(&h2);
            Xw[(l0+3) * XWST + wp] = *reinterpret_cast<uint32_t*>(&h3);
        }
        __syncthreads();

        // 65 jobs: (mt 0..12) x (slice 0..4 of 40 cols)
        for (int job = w; job < 65; job += 32) {
            int mt = job / 5, sl = job % 5;
            int cb = sl * 40;

            float acc[5][4];
            #pragma unroll
            for (int n = 0; n < 5; n++)
                #pragma unroll
                for (int j = 0; j < 4; j++) acc[n][j] = 0.f;

            const uint32_t* A0 = Xw + (mt * 16 + g) * XWST + 2 * tig;
            const uint32_t* A1 = A0 + 8 * XWST;
            const uint32_t* Bb = Xw + (cb + g) * XWST + 2 * tig;
            #pragma unroll 4
            for (int ks = 0; ks < 16; ks++) {
                uint2 av0 = *reinterpret_cast<const uint2*>(A0 + ks * 8);
                uint2 av1 = *reinterpret_cast<const uint2*>(A1 + ks * 8);
                #pragma unroll
                for (int n = 0; n < 5; n++) {
                    uint2 bv = *reinterpret_cast<const uint2*>(Bb + n * 8 * XWST + ks * 8);
                    mma16(acc[n], av0.x, av1.x, av0.y, av1.y, bv.x, bv.y);
                }
            }

            #pragma unroll
            for (int rh = 0; rh < 2; rh++) {
                int l = mt * 16 + g + 8 * rh;
                float sum = 0.f;
                #pragma unroll
                for (int n = 0; n < 5; n++) {
                    int col0 = cb + n * 8 + 2 * tig;
                    float e0 = __expf(acc[n][rh*2]);
                    float e1 = __expf(acc[n][rh*2+1]);
                    acc[n][rh*2] = e0; acc[n][rh*2+1] = e1;
                    if (col0 < Ln) sum += e0 + e1;
                }
                sum += __shfl_xor_sync(0xffffffffu, sum, 1);
                sum += __shfl_xor_sync(0xffffffffu, sum, 2);
                if (l < Ln) {
                    if (tig == 0) atomicAdd(&s_rsum[l], sum);
                    float* ar = At + (size_t)l * Ln;
                    #pragma unroll
                    for (int n = 0; n < 5; n++) {
                        int col0 = cb + n * 8 + 2 * tig;
                        if (col0 < Ln)
                            *reinterpret_cast<float2*>(ar + col0) =
                                make_float2(acc[n][rh*2], acc[n][rh*2+1]);
                    }
                }
            }
        }
    }
    __syncthreads();
    if (t < Ln) s_rsum[t] = 1.0f / s_rsum[t];
    __syncthreads();

    // ---------------- Phase 2: GEMM2 (bf16, fully-resident A+B) --------------
    {
        uint32_t* Bw = reinterpret_cast<uint32_t*>(dyn);             // 200 x WST2
        uint32_t* Aw = reinterpret_cast<uint32_t*>(dyn) + 200*WST2;  // 256 x WST2

        // stage B[m][pw(w2)] = bf16x2(exp[m][l]*rsum[l]) (symmetry), pads zero
        for (int idx = t; idx < 200 * WST2; idx += NT) {
            int m = idx / WST2, w2 = idx % WST2;
            int l0 = 2 * w2;
            uint32_t val = 0u;
            if (m < Ln && l0 < Ln) {
                float2 v = *reinterpret_cast<const float2*>(At + (size_t)m * Ln + l0);
                __nv_bfloat162 h = __floats2bfloat162_rn(v.x * s_rsum[l0], v.y * s_rsum[l0+1]);
                val = *reinterpret_cast<uint32_t*>(&h);
            }
            Bw[m * WST2 + pw8(w2)] = val;
        }
        // stage A[c][pw(w2)] = bf16x2(sam[c][l]), pads zero
        for (int idx = t; idx < 256 * WST2; idx += NT) {
            int c = idx / WST2, w2 = idx % WST2;
            int l0 = 2 * w2;
            uint32_t val = 0u;
            if (l0 < Ln) {
                float2 v = *reinterpret_cast<const float2*>(Sb + (size_t)c * Ln + l0);
                __nv_bfloat162 h = __floats2bfloat162_rn(v.x, v.y);
                val = *reinterpret_cast<uint32_t*>(&h);
            }
            Aw[c * WST2 + pw8(w2)] = val;
        }
        __syncthreads();

        // 64 jobs: (mt 0..15) x (quarter 0..3); cb {0,56,104,160}, nfr {7,6,7,5}
        #pragma unroll
        for (int r = 0; r < 2; r++) {
            int job = w + r * 32;
            int mt = job >> 2, q = job & 3;
            int cbm = (q == 0) ? 0 : (q == 1) ? 56 : (q == 2) ? 104 : 160;
            int nfr = (q == 0 || q == 2) ? 7 : (q == 1) ? 6 : 5;

            float acc[7][4];
            #pragma unroll
            for (int n = 0; n < 7; n++)
                #pragma unroll
                for (int j = 0; j < 4; j++) acc[n][j] = 0.f;

            const uint32_t* A0 = Aw + (mt * 16 + g) * WST2 + 2 * tig;
            const uint32_t* A1 = A0 + 8 * WST2;
            const uint32_t* Bb = Bw + (cbm + g) * WST2 + 2 * tig;
            #pragma unroll 4
            for (int ks = 0; ks < 13; ks++) {
                uint2 av0 = *reinterpret_cast<const uint2*>(A0 + ks * 8);
                uint2 av1 = *reinterpret_cast<const uint2*>(A1 + ks * 8);
                #pragma unroll
                for (int n = 0; n < 7; n++) {
                    if (n < nfr) {
                        uint2 bv = *reinterpret_cast<const uint2*>(Bb + n * 8 * WST2 + ks * 8);
                        mma16(acc[n], av0.x, av1.x, av0.y, av1.y, bv.x, bv.y);
                    }
                }
            }

            // epilogue: y = sam + D -> out; column stats
            int c0r = mt * 16 + g;
            int c1r = c0r + 8;
            const float* S0 = Sb + (size_t)c0r * Ln;
            const float* S1 = Sb + (size_t)c1r * Ln;
            float* O0 = out + ((size_t)b * Cn + c0r) * Ln;
            float* O1 = out + ((size_t)b * Cn + c1r) * Ln;
            #pragma unroll
            for (int n = 0; n < 7; n++) {
                if (n < nfr) {
                    int col0 = cbm + n * 8 + 2 * tig;
                    bool v = col0 < Ln;
                    float y0 = 0.f, y1 = 0.f, y2 = 0.f, y3 = 0.f;
                    if (v) {
                        float2 s0 = *reinterpret_cast<const float2*>(S0 + col0);
                        float2 s1 = *reinterpret_cast<const float2*>(S1 + col0);
                        y0 = s0.x + acc[n][0]; y1 = s0.y + acc[n][1];
                        y2 = s1.x + acc[n][2]; y3 = s1.y + acc[n][3];
                        *reinterpret_cast<float2*>(O0 + col0) = make_float2(y0, y1);
                        *reinterpret_cast<float2*>(O1 + col0) = make_float2(y2, y3);
                    }
                    float sa0 = y0 + y2, sa1 = y1 + y3;
                    float sq0 = y0*y0 + y2*y2, sq1 = y1*y1 + y3*y3;
                    #pragma unroll
                    for (int o = 4; o < 32; o <<= 1) {
                        sa0 += __shfl_xor_sync(0xffffffffu, sa0, o);
                        sa1 += __shfl_xor_sync(0xffffffffu, sa1, o);
                        sq0 += __shfl_xor_sync(0xffffffffu, sq0, o);
                        sq1 += __shfl_xor_sync(0xffffffffu, sq1, o);
                    }
                    if (g == 0 && v) {
                        atomicAdd(&cs1[col0], sa0);     atomicAdd(&cs1[col0 + 1], sa1);
                        atomicAdd(&cs2[col0], sq0);     atomicAdd(&cs2[col0 + 1], sq1);
                    }
                }
            }
        }
    }
    __syncthreads();

    // ---------------- Phase 3: channel-LN affine P,Q ----------------
    if (t < Ln) {
        float a = 0.5f * s_simw[t];
        float mu_y  = cs1[t] * (1.0f / Cn);
        float var_y = cs2[t] * (1.0f / Cn) - mu_y * mu_y;
        float inv_s = rsqrtf(a * a * var_y + 1e-5f);
        cs1[t] = a * inv_s;
        cs2[t] = -a * mu_y * inv_s;
    }
    if (t >= Ln && t < 200) { cs1[t] = 0.f; cs2[t] = 0.f; }
    __syncthreads();

    // ---------------- Phase 4: spatial standardization (out L2-hot) ----------
    {
        const float4* P4 = reinterpret_cast<const float4*>(cs1);
        const float4* Q4 = reinterpret_cast<const float4*>(cs2);
        bool has2 = (ln + 32) < Ln / 4;
        int g2 = has2 ? (ln + 32) : 0;
        float4 p0 = P4[ln], q0 = Q4[ln];
        float4 p1 = P4[g2], q1 = Q4[g2];

        for (int c = w; c < Cn; c += 32) {
            float4* orow = reinterpret_cast<float4*>(out + ((size_t)b * Cn + c) * Ln);
            float4 y0 = orow[ln];
            float x0[4] = { fmaf(y0.x, p0.x, q0.x), fmaf(y0.y, p0.y, q0.y),
                            fmaf(y0.z, p0.z, q0.z), fmaf(y0.w, p0.w, q0.w) };
            float x1[4] = { 0.f, 0.f, 0.f, 0.f };
            if (has2) {
                float4 y1 = orow[g2];
                x1[0] = fmaf(y1.x, p1.x, q1.x); x1[1] = fmaf(y1.y, p1.y, q1.y);
                x1[2] = fmaf(y1.z, p1.z, q1.z); x1[3] = fmaf(y1.w, p1.w, q1.w);
            }
            float s1 = x0[0] + x0[1] + x0[2] + x0[3];
            float s2 = x0[0]*x0[0] + x0[1]*x0[1] + x0[2]*x0[2] + x0[3]*x0[3];
            if (has2) {
                s1 += x1[0] + x1[1] + x1[2] + x1[3];
                s2 += x1[0]*x1[0] + x1[1]*x1[1] + x1[2]*x1[2] + x1[3]*x1[3];
            }
            #pragma unroll
            for (int o = 16; o > 0; o >>= 1) {
                s1 += __shfl_xor_sync(0xffffffffu, s1, o);
                s2 += __shfl_xor_sync(0xffffffffu, s2, o);
            }
            float mean = s1 * (1.0f / Ln);
            float var  = (s2 - (float)Ln * mean * mean) * (1.0f / (Ln - 1));
            float inv  = 1.0f / (sqrtf(fmaxf(var, 0.f)) + 1e-6f);

            float4 o0 = { (x0[0]-mean)*inv, (x0[1]-mean)*inv, (x0[2]-mean)*inv, (x0[3]-mean)*inv };
            orow[ln] = o0;
            if (has2) {
                float4 o1 = { (x1[0]-mean)*inv, (x1[1]-mean)*inv, (x1[2]-mean)*inv, (x1[3]-mean)*inv };
                orow[g2] = o1;
            }
        }
    }
}

// ============================================================================
extern "C" void kernel_launch(void* const* d_in, const int* in_sizes, int n_in,
                              void* d_out, int out_size)
{
    const float* imf  = (const float*)d_in[0];
    const float* txt  = (const float*)d_in[1];
    const float* sam  = (const float*)d_in[2];
    const float* Wsim = (const float*)d_in[3];
    const float* bsim = (const float*)d_in[4];
    float* out = (float*)d_out;

    // max(phase1: 208*136*4 = 113,152 ; phase2: (200+256)*104*4 = 189,696)
    const int smem = 189696;
    cudaFuncSetAttribute(k_main, cudaFuncAttributeMaxDynamicSharedMemorySize, smem);
    k_main<<<Bn, NT, smem>>>(imf, txt, sam, Wsim, bsim, out);
}

// round 11
// speedup vs baseline: 1.6406x; 1.0110x over previous
#include <cuda_runtime.h>
#include <cuda_bf16.h>
#include <math.h>
#include <stdint.h>

#define Bn 512
#define Cn 256
#define Ln 196
#define Dn 512
#define XWST 136   // phase-1 Xt word stride: 68 8B-units ≡ 4 mod 16 -> 2-way floor
#define WST2 104   // phase-2 A/B word stride
#define BOFFW 20800 // word offset of Xw / Aw region (after B: 200*104 words)

#define NT 1024    // threads per CTA (32 warps)

__device__ __forceinline__ uint32_t fu(float f) { return __float_as_uint(f); }
__device__ __forceinline__ int pw8(int w2) {    // word-perm: (word tig, tig+4) adjacent
    return (w2 & ~7) + ((w2 & 3) << 1) + ((w2 >> 2) & 1);
}

__device__ __forceinline__ void mma16(float* d, uint32_t a0, uint32_t a1, uint32_t a2,
                                      uint32_t a3, uint32_t b0, uint32_t b1) {
    asm volatile("mma.sync.aligned.m16n8k16.row.col.f32.bf16.bf16.f32 "
        "{%0,%1,%2,%3}, {%4,%5,%6,%7}, {%8,%9}, {%0,%1,%2,%3};"
        : "+f"(d[0]), "+f"(d[1]), "+f"(d[2]), "+f"(d[3])
        : "r"(a0), "r"(a1), "r"(a2), "r"(a3), "r"(b0), "r"(b1));
}

// ============================================================================
// Mega-kernel: one CTA per batch, 1024 threads (32 warps).
// smem: [Bw: 200x104 bf16x2 words][Xw: 208x136 (phase1) / Aw: 256x104 (phase2)]
// ============================================================================
__global__ __launch_bounds__(NT, 1) void k_main(
    const float* __restrict__ imf, const float* __restrict__ txt,
    const float* __restrict__ sam, const float* __restrict__ Wsim,
    const float* __restrict__ bsim, float* __restrict__ out)
{
    extern __shared__ float dyn[];          // 196,352 B
    __shared__ float s_im[Dn];
    __shared__ float red[3][32];
    __shared__ float s_simw[200];
    __shared__ __align__(16) float cs1[200];
    __shared__ __align__(16) float cs2[200];
    __shared__ __align__(16) float s_rsum[208];
    __shared__ float s_inv[256];

    int b = blockIdx.x, t = threadIdx.x, w = t >> 5, ln = t & 31;
    int g = ln >> 2, tig = ln & 3;
    const float* Sb = sam + (size_t)b * Cn * Ln;

    uint32_t* Bw = reinterpret_cast<uint32_t*>(dyn);          // 200 x WST2
    uint16_t* Bh = reinterpret_cast<uint16_t*>(dyn);          // halfword view of Bw

    // ---------------- Phase 0: simw; zero accumulators + B tile ----------------
    {
        float a0 = 0.f, c0 = 0.f;
        if (t < Dn) {
            a0 = imf[(size_t)b * Dn + t];
            c0 = txt[(size_t)b * Dn + t];
        }
        float ni = a0*a0, nt = c0*c0, ct = a0*c0;
        #pragma unroll
        for (int o = 16; o > 0; o >>= 1) {
            ni += __shfl_xor_sync(0xffffffffu, ni, o);
            nt += __shfl_xor_sync(0xffffffffu, nt, o);
            ct += __shfl_xor_sync(0xffffffffu, ct, o);
        }
        if (ln == 0) { red[0][w] = ni; red[1][w] = nt; red[2][w] = ct; }
        if (t < 200) { cs1[t] = 0.f; cs2[t] = 0.f; }
        if (t < 256) s_inv[t] = 0.f;
        if (t >= 256 && t < 464) s_rsum[t - 256] = 0.f;
        // zero B tile (pads must be 0; valid region fully overwritten later)
        {
            uint4* B4 = reinterpret_cast<uint4*>(dyn);
            for (int i = t; i < (200 * WST2) / 4; i += NT) B4[i] = make_uint4(0u,0u,0u,0u);
        }
        __syncthreads();
        float nI = 0.f, nT = 0.f, cT = 0.f;
        #pragma unroll
        for (int j = 0; j < 32; j++) { nI += red[0][j]; nT += red[1][j]; cT += red[2][j]; }
        float invI = 1.0f / fmaxf(sqrtf(nI), 1e-12f);
        float invT = 1.0f / fmaxf(sqrtf(nT), 1e-12f);
        float cross = cT * invI * invT;
        if (t < Dn) s_im[t] = imf[(size_t)b * Dn + t] * invI;
        __syncthreads();

        const float4* s4 = reinterpret_cast<const float4*>(s_im);
        for (int r = w; r < Ln; r += 32) {
            const float4* wr = reinterpret_cast<const float4*>(Wsim + (size_t)r * Dn);
            float acc = 0.f;
            #pragma unroll
            for (int i = 0; i < 4; i++) {
                float4 a = wr[ln + i * 32];
                float4 s = s4[ln + i * 32];
                acc += a.x*s.x + a.y*s.y + a.z*s.z + a.w*s.w;
            }
            #pragma unroll
            for (int o = 16; o > 0; o >>= 1) acc += __shfl_xor_sync(0xffffffffu, acc, o);
            if (ln == 0) {
                acc += bsim[r];
                s_simw[r] = cross * (1.0f / (1.0f + __expf(-acc))) * 0.1f;
            }
        }
    }
    __syncthreads();

    // ---------------- Phase 1: GEMM1 (bf16) -> bf16 raw exp -> B tile (smem) ---
    {
        uint32_t* Xw = reinterpret_cast<uint32_t*>(dyn) + BOFFW;   // 208 x XWST

        // column norms, coalesced: thread -> column l = t&255, chunk = t>>8
        {
            int l = t & 255, ch = t >> 8;
            if (l < Ln) {
                const float* p = Sb + (size_t)(ch * 64) * Ln + l;
                float s0 = 0.f, s1 = 0.f;
                #pragma unroll 8
                for (int c = 0; c < 64; c += 2) {
                    float v0 = p[c * Ln], v1 = p[(c + 1) * Ln];
                    s0 += v0 * v0; s1 += v1 * v1;
                }
                atomicAdd(&s_inv[l], s0 + s1);
            }
        }
        for (int i = t; i < 12 * XWST; i += NT) Xw[196 * XWST + i] = 0u;
        __syncthreads();
        if (t < Ln) s_inv[t] = 0.25f / fmaxf(sqrtf(s_inv[t]), 1e-12f);
        __syncthreads();

        // stage X as bf16, scaled, c-word-permuted
        for (int idx = t; idx < 128 * 49; idx += NT) {
            int c2 = idx / 49, l4 = idx % 49;
            int l0 = l4 * 4;
            float4 v0 = *reinterpret_cast<const float4*>(Sb + (size_t)(2*c2)   * Ln + l0);
            float4 v1 = *reinterpret_cast<const float4*>(Sb + (size_t)(2*c2+1) * Ln + l0);
            int wp = pw8(c2);
            float i0 = s_inv[l0], i1 = s_inv[l0+1], i2 = s_inv[l0+2], i3 = s_inv[l0+3];
            __nv_bfloat162 h0 = __floats2bfloat162_rn(v0.x * i0, v1.x * i0);
            __nv_bfloat162 h1 = __floats2bfloat162_rn(v0.y * i1, v1.y * i1);
            __nv_bfloat162 h2 = __floats2bfloat162_rn(v0.z * i2, v1.z * i2);
            __nv_bfloat162 h3 = __floats2bfloat162_rn(v0.w * i3, v1.w * i3);
            Xw[(l0+0) * XWST + wp] = *reinterpret_cast<uint32_t*>(&h0);
            Xw[(l0+1) * XWST + wp] = *reinterpret_cast<uint32_t*>(&h1);
            Xw[(l0+2) * XWST + wp] = *reinterpret_cast<uint32_t*>(&h2);
            Xw[(l0+3) * XWST + wp] = *reinterpret_cast<uint32_t*>(&h3);
        }
        __syncthreads();

        // 65 jobs: (mt 0..12) x (slice 0..4 of 40 cols)
        for (int job = w; job < 65; job += 32) {
            int mt = job / 5, sl = job % 5;
            int cb = sl * 40;

            float acc[5][4];
            #pragma unroll
            for (int n = 0; n < 5; n++)
                #pragma unroll
                for (int j = 0; j < 4; j++) acc[n][j] = 0.f;

            const uint32_t* A0 = Xw + (mt * 16 + g) * XWST + 2 * tig;
            const uint32_t* A1 = A0 + 8 * XWST;
            const uint32_t* Bb = Xw + (cb + g) * XWST + 2 * tig;
            #pragma unroll 4
            for (int ks = 0; ks < 16; ks++) {
                uint2 av0 = *reinterpret_cast<const uint2*>(A0 + ks * 8);
                uint2 av1 = *reinterpret_cast<const uint2*>(A1 + ks * 8);
                #pragma unroll
                for (int n = 0; n < 5; n++) {
                    uint2 bv = *reinterpret_cast<const uint2*>(Bb + n * 8 * XWST + ks * 8);
                    mma16(acc[n], av0.x, av1.x, av0.y, av1.y, bv.x, bv.y);
                }
            }

            // epilogue: exp -> row sums + bf16 store straight into B tile
            // (symmetry: exp[l][m] = exp[m][l]; thread writes B rows m, m+1 at k=l)
            #pragma unroll
            for (int rh = 0; rh < 2; rh++) {
                int l = mt * 16 + g + 8 * rh;
                float e[5][2];
                float sum = 0.f;
                #pragma unroll
                for (int n = 0; n < 5; n++) {
                    int col0 = cb + n * 8 + 2 * tig;
                    float e0 = __expf(acc[n][rh*2]);
                    float e1 = __expf(acc[n][rh*2+1]);
                    e[n][0] = e0; e[n][1] = e1;
                    if (col0 < Ln) sum += e0 + e1;
                }
                sum += __shfl_xor_sync(0xffffffffu, sum, 1);
                sum += __shfl_xor_sync(0xffffffffu, sum, 2);
                if (l < Ln) {
                    if (tig == 0) atomicAdd(&s_rsum[l], sum);
                    int hw = pw8(l >> 1) * 2 + (l & 1);
                    #pragma unroll
                    for (int n = 0; n < 5; n++) {
                        int col0 = cb + n * 8 + 2 * tig;
                        if (col0 < Ln) {
                            __nv_bfloat16 h0 = __float2bfloat16(e[n][0]);
                            __nv_bfloat16 h1 = __float2bfloat16(e[n][1]);
                            Bh[col0 * (2 * WST2) + hw]       = *reinterpret_cast<uint16_t*>(&h0);
                            Bh[(col0 + 1) * (2 * WST2) + hw] = *reinterpret_cast<uint16_t*>(&h1);
                        }
                    }
                }
            }
        }
    }
    __syncthreads();
    if (t < Ln) s_rsum[t] = 1.0f / s_rsum[t];
    __syncthreads();

    // ---------------- Phase 2: GEMM2 (bf16); B already resident ----------------
    {
        uint32_t* Aw = reinterpret_cast<uint32_t*>(dyn) + BOFFW;   // 256 x WST2

        // stage A'[c][pw(w2)] = bf16x2(sam[c][l] / rsum[l])  (1/rsum folded here)
        for (int idx = t; idx < 256 * WST2; idx += NT) {
            int c = idx / WST2, w2 = idx % WST2;
            int l0 = 2 * w2;
            uint32_t val = 0u;
            if (l0 < Ln) {
                float2 v = *reinterpret_cast<const float2*>(Sb + (size_t)c * Ln + l0);
                float2 r = *reinterpret_cast<const float2*>(&s_rsum[l0]);
                __nv_bfloat162 h = __floats2bfloat162_rn(v.x * r.x, v.y * r.y);
                val = *reinterpret_cast<uint32_t*>(&h);
            }
            Aw[c * WST2 + pw8(w2)] = val;
        }
        __syncthreads();

        // 64 jobs: (mt 0..15) x (quarter 0..3); cb {0,56,104,160}, nfr {7,6,7,5}
        #pragma unroll
        for (int r = 0; r < 2; r++) {
            int job = w + r * 32;
            int mt = job >> 2, q = job & 3;
            int cbm = (q == 0) ? 0 : (q == 1) ? 56 : (q == 2) ? 104 : 160;
            int nfr = (q == 0 || q == 2) ? 7 : (q == 1) ? 6 : 5;

            float acc[7][4];
            #pragma unroll
            for (int n = 0; n < 7; n++)
                #pragma unroll
                for (int j = 0; j < 4; j++) acc[n][j] = 0.f;

            const uint32_t* A0 = Aw + (mt * 16 + g) * WST2 + 2 * tig;
            const uint32_t* A1 = A0 + 8 * WST2;
            const uint32_t* Bb = Bw + (cbm + g) * WST2 + 2 * tig;
            #pragma unroll 4
            for (int ks = 0; ks < 13; ks++) {
                uint2 av0 = *reinterpret_cast<const uint2*>(A0 + ks * 8);
                uint2 av1 = *reinterpret_cast<const uint2*>(A1 + ks * 8);
                #pragma unroll
                for (int n = 0; n < 7; n++) {
                    if (n < nfr) {
                        uint2 bv = *reinterpret_cast<const uint2*>(Bb + n * 8 * WST2 + ks * 8);
                        mma16(acc[n], av0.x, av1.x, av0.y, av1.y, bv.x, bv.y);
                    }
                }
            }

            // epilogue: y = sam + D -> out; column stats
            int c0r = mt * 16 + g;
            int c1r = c0r + 8;
            const float* S0 = Sb + (size_t)c0r * Ln;
            const float* S1 = Sb + (size_t)c1r * Ln;
            float* O0 = out + ((size_t)b * Cn + c0r) * Ln;
            float* O1 = out + ((size_t)b * Cn + c1r) * Ln;
            #pragma unroll
            for (int n = 0; n < 7; n++) {
                if (n < nfr) {
                    int col0 = cbm + n * 8 + 2 * tig;
                    bool v = col0 < Ln;
                    float y0 = 0.f, y1 = 0.f, y2 = 0.f, y3 = 0.f;
                    if (v) {
                        float2 s0 = *reinterpret_cast<const float2*>(S0 + col0);
                        float2 s1 = *reinterpret_cast<const float2*>(S1 + col0);
                        y0 = s0.x + acc[n][0]; y1 = s0.y + acc[n][1];
                        y2 = s1.x + acc[n][2]; y3 = s1.y + acc[n][3];
                        *reinterpret_cast<float2*>(O0 + col0) = make_float2(y0, y1);
                        *reinterpret_cast<float2*>(O1 + col0) = make_float2(y2, y3);
                    }
                    float sa0 = y0 + y2, sa1 = y1 + y3;
                    float sq0 = y0*y0 + y2*y2, sq1 = y1*y1 + y3*y3;
                    #pragma unroll
                    for (int o = 4; o < 32; o <<= 1) {
                        sa0 += __shfl_xor_sync(0xffffffffu, sa0, o);
                        sa1 += __shfl_xor_sync(0xffffffffu, sa1, o);
                        sq0 += __shfl_xor_sync(0xffffffffu, sq0, o);
                        sq1 += __shfl_xor_sync(0xffffffffu, sq1, o);
                    }
                    if (g == 0 && v) {
                        atomicAdd(&cs1[col0], sa0);     atomicAdd(&cs1[col0 + 1], sa1);
                        atomicAdd(&cs2[col0], sq0);     atomicAdd(&cs2[col0 + 1], sq1);
                    }
                }
            }
        }
    }
    __syncthreads();

    // ---------------- Phase 3: channel-LN affine P,Q ----------------
    if (t < Ln) {
        float a = 0.5f * s_simw[t];
        float mu_y  = cs1[t] * (1.0f / Cn);
        float var_y = cs2[t] * (1.0f / Cn) - mu_y * mu_y;
        float inv_s = rsqrtf(a * a * var_y + 1e-5f);
        cs1[t] = a * inv_s;
        cs2[t] = -a * mu_y * inv_s;
    }
    if (t >= Ln && t < 200) { cs1[t] = 0.f; cs2[t] = 0.f; }
    __syncthreads();

    // ---------------- Phase 4: spatial standardization (out L2-hot) ----------
    {
        const float4* P4 = reinterpret_cast<const float4*>(cs1);
        const float4* Q4 = reinterpret_cast<const float4*>(cs2);
        bool has2 = (ln + 32) < Ln / 4;
        int g2 = has2 ? (ln + 32) : 0;
        float4 p0 = P4[ln], q0 = Q4[ln];
        float4 p1 = P4[g2], q1 = Q4[g2];

        for (int c = w; c < Cn; c += 32) {
            float4* orow = reinterpret_cast<float4*>(out + ((size_t)b * Cn + c) * Ln);
            float4 y0 = orow[ln];
            float x0[4] = { fmaf(y0.x, p0.x, q0.x), fmaf(y0.y, p0.y, q0.y),
                            fmaf(y0.z, p0.z, q0.z), fmaf(y0.w, p0.w, q0.w) };
            float x1[4] = { 0.f, 0.f, 0.f, 0.f };
            if (has2) {
                float4 y1 = orow[g2];
                x1[0] = fmaf(y1.x, p1.x, q1.x); x1[1] = fmaf(y1.y, p1.y, q1.y);
                x1[2] = fmaf(y1.z, p1.z, q1.z); x1[3] = fmaf(y1.w, p1.w, q1.w);
            }
            float s1 = x0[0] + x0[1] + x0[2] + x0[3];
            float s2 = x0[0]*x0[0] + x0[1]*x0[1] + x0[2]*x0[2] + x0[3]*x0[3];
            if (has2) {
                s1 += x1[0] + x1[1] + x1[2] + x1[3];
                s2 += x1[0]*x1[0] + x1[1]*x1[1] + x1[2]*x1[2] + x1[3]*x1[3];
            }
            #pragma unroll
            for (int o = 16; o > 0; o >>= 1) {
                s1 += __shfl_xor_sync(0xffffffffu, s1, o);
                s2 += __shfl_xor_sync(0xffffffffu, s2, o);
            }
            float mean = s1 * (1.0f / Ln);
            float var  = (s2 - (float)Ln * mean * mean) * (1.0f / (Ln - 1));
            float inv  = 1.0f / (sqrtf(fmaxf(var, 0.f)) + 1e-6f);

            float4 o0 = { (x0[0]-mean)*inv, (x0[1]-mean)*inv, (x0[2]-mean)*inv, (x0[3]-mean)*inv };
            orow[ln] = o0;
            if (has2) {
                float4 o1 = { (x1[0]-mean)*inv, (x1[1]-mean)*inv, (x1[2]-mean)*inv, (x1[3]-mean)*inv };
                orow[g2] = o1;
            }
        }
    }
}

// ============================================================================
extern "C" void kernel_launch(void* const* d_in, const int* in_sizes, int n_in,
                              void* d_out, int out_size)
{
    const float* imf  = (const float*)d_in[0];
    const float* txt  = (const float*)d_in[1];
    const float* sam  = (const float*)d_in[2];
    const float* Wsim = (const float*)d_in[3];
    const float* bsim = (const float*)d_in[4];
    float* out = (float*)d_out;

    // B (200*104 words) + max(Xw 208*136, Aw 256*104) words = 49,088 words
    const int smem = (BOFFW + 208 * XWST) * (int)sizeof(float);   // 196,352 B
    cudaFuncSetAttribute(k_main, cudaFuncAttributeMaxDynamicSharedMemorySize, smem);
    k_main<<<Bn, NT, smem>>>(imf, txt, sam, Wsim, bsim, out);
}

// round 12
// speedup vs baseline: 1.6798x; 1.0239x over previous
#include <cuda_runtime.h>
#include <cuda_bf16.h>
#include <math.h>
#include <stdint.h>

#define Bn 512
#define Cn 256
#define Ln 196
#define Dn 512
#define XWST 136   // phase-1 Xt word stride: 68 8B-units ≡ 4 mod 16 -> 2-way floor
#define WST2 104   // phase-2 A/B word stride
#define BOFFW 20800 // word offset of Xw / Aw region (after B: 200*104 words)

#define NT 1024    // threads per CTA (32 warps)

__device__ __forceinline__ uint32_t fu(float f) { return __float_as_uint(f); }
__device__ __forceinline__ int pw8(int w2) {    // word-perm: (word tig, tig+4) adjacent
    return (w2 & ~7) + ((w2 & 3) << 1) + ((w2 >> 2) & 1);
}

__device__ __forceinline__ void mma16(float* d, uint32_t a0, uint32_t a1, uint32_t a2,
                                      uint32_t a3, uint32_t b0, uint32_t b1) {
    asm volatile("mma.sync.aligned.m16n8k16.row.col.f32.bf16.bf16.f32 "
        "{%0,%1,%2,%3}, {%4,%5,%6,%7}, {%8,%9}, {%0,%1,%2,%3};"
        : "+f"(d[0]), "+f"(d[1]), "+f"(d[2]), "+f"(d[3])
        : "r"(a0), "r"(a1), "r"(a2), "r"(a3), "r"(b0), "r"(b1));
}

// ============================================================================
// Mega-kernel: one CTA per batch, 1024 threads (32 warps).
// smem: [Bw: 200x104 bf16x2 words][Xw: 208x136 (phase1) / Aw: 256x104 (phase2)]
// ============================================================================
__global__ __launch_bounds__(NT, 1) void k_main(
    const float* __restrict__ imf, const float* __restrict__ txt,
    const float* __restrict__ sam, const float* __restrict__ Wsim,
    const float* __restrict__ bsim, float* __restrict__ out)
{
    extern __shared__ float dyn[];          // 196,352 B
    __shared__ float s_im[Dn];
    __shared__ float red[3][32];
    __shared__ float s_simw[200];
    __shared__ __align__(16) float cs1[200];
    __shared__ __align__(16) float cs2[200];
    __shared__ __align__(16) float s_rsum[208];
    __shared__ float s_inv[256];

    int b = blockIdx.x, t = threadIdx.x, w = t >> 5, ln = t & 31;
    int g = ln >> 2, tig = ln & 3;
    const float* Sb = sam + (size_t)b * Cn * Ln;

    uint32_t* Bw = reinterpret_cast<uint32_t*>(dyn);          // 200 x WST2
    uint16_t* Bh = reinterpret_cast<uint16_t*>(dyn);          // halfword view of Bw

    // ---------------- Phase 0: simw; zero accumulators + B tile ----------------
    {
        float a0 = 0.f, c0 = 0.f;
        if (t < Dn) {
            a0 = imf[(size_t)b * Dn + t];
            c0 = txt[(size_t)b * Dn + t];
        }
        float ni = a0*a0, nt = c0*c0, ct = a0*c0;
        #pragma unroll
        for (int o = 16; o > 0; o >>= 1) {
            ni += __shfl_xor_sync(0xffffffffu, ni, o);
            nt += __shfl_xor_sync(0xffffffffu, nt, o);
            ct += __shfl_xor_sync(0xffffffffu, ct, o);
        }
        if (ln == 0) { red[0][w] = ni; red[1][w] = nt; red[2][w] = ct; }
        if (t < 200) { cs1[t] = 0.f; cs2[t] = 0.f; }
        if (t < 256) s_inv[t] = 0.f;
        if (t >= 256 && t < 464) s_rsum[t - 256] = 0.f;
        // zero B tile (pads must be 0; valid region fully overwritten later)
        {
            uint4* B4 = reinterpret_cast<uint4*>(dyn);
            for (int i = t; i < (200 * WST2) / 4; i += NT) B4[i] = make_uint4(0u,0u,0u,0u);
        }
        __syncthreads();
        float nI = 0.f, nT = 0.f, cT = 0.f;
        #pragma unroll
        for (int j = 0; j < 32; j++) { nI += red[0][j]; nT += red[1][j]; cT += red[2][j]; }
        float invI = 1.0f / fmaxf(sqrtf(nI), 1e-12f);
        float invT = 1.0f / fmaxf(sqrtf(nT), 1e-12f);
        float cross = cT * invI * invT;
        if (t < Dn) s_im[t] = imf[(size_t)b * Dn + t] * invI;
        __syncthreads();

        const float4* s4 = reinterpret_cast<const float4*>(s_im);
        for (int r = w; r < Ln; r += 32) {
            const float4* wr = reinterpret_cast<const float4*>(Wsim + (size_t)r * Dn);
            float acc = 0.f;
            #pragma unroll
            for (int i = 0; i < 4; i++) {
                float4 a = wr[ln + i * 32];
                float4 s = s4[ln + i * 32];
                acc += a.x*s.x + a.y*s.y + a.z*s.z + a.w*s.w;
            }
            #pragma unroll
            for (int o = 16; o > 0; o >>= 1) acc += __shfl_xor_sync(0xffffffffu, acc, o);
            if (ln == 0) {
                acc += bsim[r];
                s_simw[r] = cross * (1.0f / (1.0f + __expf(-acc))) * 0.1f;
            }
        }
    }
    __syncthreads();

    // ---------------- Phase 1: GEMM1 (bf16) -> bf16 raw exp -> B tile (smem) ---
    {
        uint32_t* Xw = reinterpret_cast<uint32_t*>(dyn) + BOFFW;   // 208 x XWST

        // column norms, coalesced: thread -> column l = t&255, chunk = t>>8
        {
            int l = t & 255, ch = t >> 8;
            if (l < Ln) {
                const float* p = Sb + (size_t)(ch * 64) * Ln + l;
                float s0 = 0.f, s1 = 0.f;
                #pragma unroll 8
                for (int c = 0; c < 64; c += 2) {
                    float v0 = p[c * Ln], v1 = p[(c + 1) * Ln];
                    s0 += v0 * v0; s1 += v1 * v1;
                }
                atomicAdd(&s_inv[l], s0 + s1);
            }
        }
        for (int i = t; i < 12 * XWST; i += NT) Xw[196 * XWST + i] = 0u;
        __syncthreads();
        if (t < Ln) s_inv[t] = 0.25f / fmaxf(sqrtf(s_inv[t]), 1e-12f);
        __syncthreads();

        // stage X as bf16, scaled, c-word-permuted (incremental index: 1024=20*49+44)
        {
            int c2 = t / 49, l4 = t - c2 * 49;
            for (int idx = t; idx < 128 * 49; idx += NT) {
                int l0 = l4 * 4;
                float4 v0 = *reinterpret_cast<const float4*>(Sb + (size_t)(2*c2)   * Ln + l0);
                float4 v1 = *reinterpret_cast<const float4*>(Sb + (size_t)(2*c2+1) * Ln + l0);
                int wp = pw8(c2);
                float i0 = s_inv[l0], i1 = s_inv[l0+1], i2 = s_inv[l0+2], i3 = s_inv[l0+3];
                __nv_bfloat162 h0 = __floats2bfloat162_rn(v0.x * i0, v1.x * i0);
                __nv_bfloat162 h1 = __floats2bfloat162_rn(v0.y * i1, v1.y * i1);
                __nv_bfloat162 h2 = __floats2bfloat162_rn(v0.z * i2, v1.z * i2);
                __nv_bfloat162 h3 = __floats2bfloat162_rn(v0.w * i3, v1.w * i3);
                Xw[(l0+0) * XWST + wp] = *reinterpret_cast<uint32_t*>(&h0);
                Xw[(l0+1) * XWST + wp] = *reinterpret_cast<uint32_t*>(&h1);
                Xw[(l0+2) * XWST + wp] = *reinterpret_cast<uint32_t*>(&h2);
                Xw[(l0+3) * XWST + wp] = *reinterpret_cast<uint32_t*>(&h3);
                l4 += 44; c2 += 20;
                if (l4 >= 49) { l4 -= 49; c2 += 1; }
            }
        }
        __syncthreads();

        // 65 jobs: (mt 0..12) x (slice 0..4 of 40 cols)
        for (int job = w; job < 65; job += 32) {
            int mt = job / 5, sl = job % 5;
            int cb = sl * 40;

            float acc[5][4];
            #pragma unroll
            for (int n = 0; n < 5; n++)
                #pragma unroll
                for (int j = 0; j < 4; j++) acc[n][j] = 0.f;

            const uint32_t* A0 = Xw + (mt * 16 + g) * XWST + 2 * tig;
            const uint32_t* A1 = A0 + 8 * XWST;
            const uint32_t* Bb = Xw + (cb + g) * XWST + 2 * tig;
            #pragma unroll 4
            for (int ks = 0; ks < 16; ks++) {
                uint2 av0 = *reinterpret_cast<const uint2*>(A0 + ks * 8);
                uint2 av1 = *reinterpret_cast<const uint2*>(A1 + ks * 8);
                #pragma unroll
                for (int n = 0; n < 5; n++) {
                    uint2 bv = *reinterpret_cast<const uint2*>(Bb + n * 8 * XWST + ks * 8);
                    mma16(acc[n], av0.x, av1.x, av0.y, av1.y, bv.x, bv.y);
                }
            }

            // epilogue: exp -> row sums + bf16 store straight into B tile
            // (symmetry: exp[l][m] = exp[m][l]; thread writes B rows m, m+1 at k=l)
            #pragma unroll
            for (int rh = 0; rh < 2; rh++) {
                int l = mt * 16 + g + 8 * rh;
                float e[5][2];
                float sum = 0.f;
                #pragma unroll
                for (int n = 0; n < 5; n++) {
                    int col0 = cb + n * 8 + 2 * tig;
                    float e0 = __expf(acc[n][rh*2]);
                    float e1 = __expf(acc[n][rh*2+1]);
                    e[n][0] = e0; e[n][1] = e1;
                    if (col0 < Ln) sum += e0 + e1;
                }
                sum += __shfl_xor_sync(0xffffffffu, sum, 1);
                sum += __shfl_xor_sync(0xffffffffu, sum, 2);
                if (l < Ln) {
                    if (tig == 0) atomicAdd(&s_rsum[l], sum);
                    int hw = pw8(l >> 1) * 2 + (l & 1);
                    #pragma unroll
                    for (int n = 0; n < 5; n++) {
                        int col0 = cb + n * 8 + 2 * tig;
                        if (col0 < Ln) {
                            __nv_bfloat16 h0 = __float2bfloat16(e[n][0]);
                            __nv_bfloat16 h1 = __float2bfloat16(e[n][1]);
                            Bh[col0 * (2 * WST2) + hw]       = *reinterpret_cast<uint16_t*>(&h0);
                            Bh[(col0 + 1) * (2 * WST2) + hw] = *reinterpret_cast<uint16_t*>(&h1);
                        }
                    }
                }
            }
        }
    }
    __syncthreads();
    if (t < Ln) s_rsum[t] = 1.0f / s_rsum[t];
    __syncthreads();

    // ---------------- Phase 2: GEMM2 (bf16); B already resident ----------------
    {
        uint32_t* Aw = reinterpret_cast<uint32_t*>(dyn) + BOFFW;   // 256 x WST2

        // stage A'[c][pw(w2)] = bf16x2(sam[c][l] / rsum[l]); vectorized,
        // incremental index over (c, g4): 6656 iters total, 1024 = 39*26 + 10
        {
            int c = t / 26, g4 = t - c * 26;
            for (int idx = t; idx < 256 * 26; idx += NT) {
                int l0 = g4 * 8;
                float4 va = make_float4(0.f, 0.f, 0.f, 0.f);
                float4 vb = make_float4(0.f, 0.f, 0.f, 0.f);
                const float* src = Sb + (size_t)c * Ln + l0;
                if (l0 < Ln) va = *reinterpret_cast<const float4*>(src);
                if (l0 + 4 < Ln) vb = *reinterpret_cast<const float4*>(src + 4);
                float4 r0 = *reinterpret_cast<const float4*>(s_rsum + l0);
                float4 r1 = *reinterpret_cast<const float4*>(s_rsum + l0 + 4);
                __nv_bfloat162 h0 = __floats2bfloat162_rn(va.x * r0.x, va.y * r0.y);
                __nv_bfloat162 h1 = __floats2bfloat162_rn(va.z * r0.z, va.w * r0.w);
                __nv_bfloat162 h2 = __floats2bfloat162_rn(vb.x * r1.x, vb.y * r1.y);
                __nv_bfloat162 h3 = __floats2bfloat162_rn(vb.z * r1.z, vb.w * r1.w);
                uint32_t* dst = Aw + c * WST2;
                int w2 = g4 * 4;
                dst[pw8(w2)]     = *reinterpret_cast<uint32_t*>(&h0);
                dst[pw8(w2 + 1)] = *reinterpret_cast<uint32_t*>(&h1);
                dst[pw8(w2 + 2)] = *reinterpret_cast<uint32_t*>(&h2);
                dst[pw8(w2 + 3)] = *reinterpret_cast<uint32_t*>(&h3);
                g4 += 10; c += 39;
                if (g4 >= 26) { g4 -= 26; c += 1; }
            }
        }
        __syncthreads();

        // 64 jobs: (mt 0..15) x (quarter 0..3); cb {0,56,104,160}, nfr {7,6,7,5}
        #pragma unroll
        for (int r = 0; r < 2; r++) {
            int job = w + r * 32;
            int mt = job >> 2, q = job & 3;
            int cbm = (q == 0) ? 0 : (q == 1) ? 56 : (q == 2) ? 104 : 160;
            int nfr = (q == 0 || q == 2) ? 7 : (q == 1) ? 6 : 5;

            float acc[7][4];
            #pragma unroll
            for (int n = 0; n < 7; n++)
                #pragma unroll
                for (int j = 0; j < 4; j++) acc[n][j] = 0.f;

            const uint32_t* A0 = Aw + (mt * 16 + g) * WST2 + 2 * tig;
            const uint32_t* A1 = A0 + 8 * WST2;
            const uint32_t* Bb = Bw + (cbm + g) * WST2 + 2 * tig;
            #pragma unroll 4
            for (int ks = 0; ks < 13; ks++) {
                uint2 av0 = *reinterpret_cast<const uint2*>(A0 + ks * 8);
                uint2 av1 = *reinterpret_cast<const uint2*>(A1 + ks * 8);
                #pragma unroll
                for (int n = 0; n < 7; n++) {
                    if (n < nfr) {
                        uint2 bv = *reinterpret_cast<const uint2*>(Bb + n * 8 * WST2 + ks * 8);
                        mma16(acc[n], av0.x, av1.x, av0.y, av1.y, bv.x, bv.y);
                    }
                }
            }

            // epilogue: y = sam + D -> out ONLY (stats moved to coalesced pass)
            int c0r = mt * 16 + g;
            int c1r = c0r + 8;
            const float* S0 = Sb + (size_t)c0r * Ln;
            const float* S1 = Sb + (size_t)c1r * Ln;
            float* O0 = out + ((size_t)b * Cn + c0r) * Ln;
            float* O1 = out + ((size_t)b * Cn + c1r) * Ln;
            #pragma unroll
            for (int n = 0; n < 7; n++) {
                if (n < nfr) {
                    int col0 = cbm + n * 8 + 2 * tig;
                    if (col0 < Ln) {
                        float2 s0 = *reinterpret_cast<const float2*>(S0 + col0);
                        float2 s1 = *reinterpret_cast<const float2*>(S1 + col0);
                        *reinterpret_cast<float2*>(O0 + col0) =
                            make_float2(s0.x + acc[n][0], s0.y + acc[n][1]);
                        *reinterpret_cast<float2*>(O1 + col0) =
                            make_float2(s1.x + acc[n][2], s1.y + acc[n][3]);
                    }
                }
            }
        }
    }
    __syncthreads();

    // ---------------- Phase 2b: column stats from out (L2-hot, coalesced) ------
    {
        int l = t & 255, ch = t >> 8;       // ch in 0..3, 64 rows each
        if (l < Ln) {
            const float* p = out + (size_t)b * Cn * Ln + (size_t)(ch * 64) * Ln + l;
            float s1 = 0.f, s2 = 0.f;
            #pragma unroll 8
            for (int c = 0; c < 64; c += 2) {
                float v0 = p[c * Ln], v1 = p[(c + 1) * Ln];
                s1 += v0 + v1;
                s2 += v0 * v0 + v1 * v1;
            }
            atomicAdd(&cs1[l], s1);
            atomicAdd(&cs2[l], s2);
        }
    }
    __syncthreads();

    // ---------------- Phase 3: channel-LN affine P,Q ----------------
    if (t < Ln) {
        float a = 0.5f * s_simw[t];
        float mu_y  = cs1[t] * (1.0f / Cn);
        float var_y = cs2[t] * (1.0f / Cn) - mu_y * mu_y;
        float inv_s = rsqrtf(a * a * var_y + 1e-5f);
        cs1[t] = a * inv_s;
        cs2[t] = -a * mu_y * inv_s;
    }
    if (t >= Ln && t < 200) { cs1[t] = 0.f; cs2[t] = 0.f; }
    __syncthreads();

    // ---------------- Phase 4: spatial standardization (out L2-hot) ----------
    {
        const float4* P4 = reinterpret_cast<const float4*>(cs1);
        const float4* Q4 = reinterpret_cast<const float4*>(cs2);
        bool has2 = (ln + 32) < Ln / 4;
        int g2 = has2 ? (ln + 32) : 0;
        float4 p0 = P4[ln], q0 = Q4[ln];
        float4 p1 = P4[g2], q1 = Q4[g2];

        for (int c = w; c < Cn; c += 32) {
            float4* orow = reinterpret_cast<float4*>(out + ((size_t)b * Cn + c) * Ln);
            float4 y0 = orow[ln];
            float x0[4] = { fmaf(y0.x, p0.x, q0.x), fmaf(y0.y, p0.y, q0.y),
                            fmaf(y0.z, p0.z, q0.z), fmaf(y0.w, p0.w, q0.w) };
            float x1[4] = { 0.f, 0.f, 0.f, 0.f };
            if (has2) {
                float4 y1 = orow[g2];
                x1[0] = fmaf(y1.x, p1.x, q1.x); x1[1] = fmaf(y1.y, p1.y, q1.y);
                x1[2] = fmaf(y1.z, p1.z, q1.z); x1[3] = fmaf(y1.w, p1.w, q1.w);
            }
            float s1 = x0[0] + x0[1] + x0[2] + x0[3];
            float s2 = x0[0]*x0[0] + x0[1]*x0[1] + x0[2]*x0[2] + x0[3]*x0[3];
            if (has2) {
                s1 += x1[0] + x1[1] + x1[2] + x1[3];
                s2 += x1[0]*x1[0] + x1[1]*x1[1] + x1[2]*x1[2] + x1[3]*x1[3];
            }
            #pragma unroll
            for (int o = 16; o > 0; o >>= 1) {
                s1 += __shfl_xor_sync(0xffffffffu, s1, o);
                s2 += __shfl_xor_sync(0xffffffffu, s2, o);
            }
            float mean = s1 * (1.0f / Ln);
            float var  = (s2 - (float)Ln * mean * mean) * (1.0f / (Ln - 1));
            float inv  = 1.0f / (sqrtf(fmaxf(var, 0.f)) + 1e-6f);

            float4 o0 = { (x0[0]-mean)*inv, (x0[1]-mean)*inv, (x0[2]-mean)*inv, (x0[3]-mean)*inv };
            orow[ln] = o0;
            if (has2) {
                float4 o1 = { (x1[0]-mean)*inv, (x1[1]-mean)*inv, (x1[2]-mean)*inv, (x1[3]-mean)*inv };
                orow[g2] = o1;
            }
        }
    }
}

// ============================================================================
extern "C" void kernel_launch(void* const* d_in, const int* in_sizes, int n_in,
                              void* d_out, int out_size)
{
    const float* imf  = (const float*)d_in[0];
    const float* txt  = (const float*)d_in[1];
    const float* sam  = (const float*)d_in[2];
    const float* Wsim = (const float*)d_in[3];
    const float* bsim = (const float*)d_in[4];
    float* out = (float*)d_out;

    // B (200*104 words) + max(Xw 208*136, Aw 256*104) words = 49,088 words
    const int smem = (BOFFW + 208 * XWST) * (int)sizeof(float);   // 196,352 B
    cudaFuncSetAttribute(k_main, cudaFuncAttributeMaxDynamicSharedMemorySize, smem);
    k_main<<<Bn, NT, smem>>>(imf, txt, sam, Wsim, bsim, out);
}